// round 10
// baseline (speedup 1.0000x reference)
#include <cuda_runtime.h>
#include <math.h>

#define T_STEPS 512
#define B_SZ    128
#define BT      (B_SZ * T_STEPS)
#define OUT_D   1442
#define NCTA    128

typedef unsigned long long ull;

// ---------------- scratch (static device globals; no allocation) ----------------
__device__ __align__(16) float g_oproj[BT * 256];          // obs @ W1o + post_b1, [B][T][256]
__device__ __align__(16) float g_hid3 [(size_t)BT * 1024]; // merged decoder hidden
__device__ __align__(16) float g_WihT [768 * 304];         // W_ih transposed: [n][k]
__device__ __align__(16) float g_WhhT [768 * 256];         // W_hh transposed: [n][k]
__device__ __align__(16) float g_Wcat [288 * 1024];        // merged decoder L1 weights
__device__ __align__(16) float g_bcat [1024];
__device__ __align__(16) float g_part [B_SZ * 16 * 64];    // partial o64: [b][jt][64]
__device__ __align__(16) float g_state[B_SZ * 256];        // h only
__device__ unsigned g_cnts[8 * 32];                        // per-group barrier counters (128B apart)

__device__ __forceinline__ float sigmoidf_(float x) { return 1.f / (1.f + expf(-x)); }
__device__ __forceinline__ float softplusf_(float x) {
    return fmaxf(x, 0.f) + log1pf(expf(-fabsf(x)));
}

// packed fp32x2 helpers (exact fp32 math, 2 FMAs per issue)
__device__ __forceinline__ void fma2(ull& d, ull a, ull b) {
    asm("fma.rn.f32x2 %0, %1, %2, %0;" : "+l"(d) : "l"(a), "l"(b));
}
__device__ __forceinline__ void add2(ull& d, ull a) {
    asm("add.rn.f32x2 %0, %0, %1;" : "+l"(d) : "l"(a));
}
__device__ __forceinline__ ull pack2(float lo, float hi) {
    ull r; asm("mov.b64 %0, {%1, %2};" : "=l"(r) : "f"(lo), "f"(hi)); return r;
}
__device__ __forceinline__ float2 unpack2(ull v) {
    float2 f; asm("mov.b64 {%0, %1}, %2;" : "=f"(f.x), "=f"(f.y) : "l"(v)); return f;
}

// L2-direct loads (bypass L1 -> always fresh after acquire)
__device__ __forceinline__ float4 ldcg4(const float* p) {
    float4 v;
    asm volatile("ld.global.cg.v4.f32 {%0,%1,%2,%3}, [%4];"
                 : "=f"(v.x), "=f"(v.y), "=f"(v.z), "=f"(v.w) : "l"(p));
    return v;
}
__device__ __forceinline__ float ldcg1(const float* p) {
    float v;
    asm volatile("ld.global.cg.f32 %0, [%1];" : "=f"(v) : "l"(p));
    return v;
}

// scoped-atomic barrier primitives (no MEMBAR.GL)
__device__ __forceinline__ void bar_arrive(unsigned* cnt) {
    if (threadIdx.x == 0)
        asm volatile("red.release.gpu.global.add.u32 [%0], %1;" :: "l"(cnt), "r"(1u) : "memory");
}
__device__ __forceinline__ void bar_wait(unsigned* cnt, unsigned target) {
    if (threadIdx.x == 0) {
        unsigned v;
        do {
            asm volatile("ld.acquire.gpu.global.u32 %0, [%1];" : "=r"(v) : "l"(cnt) : "memory");
        } while (v < target);
    }
    __syncthreads();
}

// ---------------- prep: transpose GRU weights, reset barriers ----------------
__global__ void prep_kernel(const float* __restrict__ W_ih, const float* __restrict__ W_hh) {
    if (blockIdx.x == 0 && threadIdx.x < 8) g_cnts[threadIdx.x * 32] = 0u;
    int idx = blockIdx.x * 256 + threadIdx.x;
    const int n1 = 768 * 304;
    if (idx < n1) {
        int n = idx / 304, k = idx - n * 304;
        g_WihT[idx] = W_ih[k * 768 + n];
    } else {
        int r = idx - n1;            // exact grid: r < 768*256
        int n = r >> 8, k = r & 255;
        g_WhhT[r] = W_hh[k * 768 + n];
    }
}

// build Wcat[288][1024]
__global__ void prep2_kernel(const float* __restrict__ prior_W1, const float* __restrict__ prior_b1,
                             const float* __restrict__ dobs_W1,  const float* __restrict__ dobs_b1,
                             const float* __restrict__ drew_W1,  const float* __restrict__ drew_b1,
                             const float* __restrict__ dcont_W1, const float* __restrict__ dcont_b1)
{
    int idx = blockIdx.x * 256 + threadIdx.x;      // 288*1024 grid
    int k = idx >> 10, j = idx & 1023;
    int g = j >> 8, jj = j & 255;
    float v;
    if (g == 0)      v = (k < 256) ? prior_W1[k * 256 + jj] : 0.f;
    else if (g == 1) v = dobs_W1[(size_t)k * 256 + jj];
    else if (g == 2) v = drew_W1[(size_t)k * 256 + jj];
    else             v = dcont_W1[(size_t)k * 256 + jj];
    g_Wcat[idx] = v;
    if (idx < 1024) {
        float b;
        if (g == 0)      b = prior_b1[jj];
        else if (g == 1) b = dobs_b1[jj];
        else if (g == 2) b = drew_b1[jj];
        else             b = dcont_b1[jj];
        g_bcat[idx] = b;
    }
}

// ---------------- persistent scan kernel: 512 threads, gate-split ----------------
// 128 CTAs x 512 threads. CTA c: jt = c & 15 (16 h-cols), bt = c >> 4 (16 batch rows).
// 8 independent bt-groups; barriers via scoped atomics (16 arrivals each).
// Thread map: bl = tid&15 (row), jl = (tid>>4)&15 (col), q = tid>>8 (gate half).
#define SM_WGRU 0
#define SM_W1H  26880
#define SM_W2   (SM_W1H + 16*260)           // 31040
#define SM_B2   (SM_W2 + 16384)             // 47424
#define SM_XS   (SM_B2 + 64)                // 47488  (xs: 16 x 308)
#define SM_HST  (SM_XS + 16*308)            // 52416  (hst: 16 x 17)
#define SM_O64  (SM_HST + 16*17)            // 52688  (o64s: 16 x 64)
#define SM_STG  (SM_O64 + 1024)             // 53712  (pm/ps/z staging: 16 x 96)
#define SM_EBUF (SM_STG + 16*96)            // 55248  (eps prefetch: 512)
#define SM_ABUF (SM_EBUF + 512)             // 55760  (act prefetch: 256)
#define SM_GT   (SM_ABUF + 256)             // 56016  (gate scratch: 16*16*4)
#define SM_OB   (SM_GT + 1024)              // 57040  (oproj buf: 256)
#define SM_FLOATS (SM_OB + 256)             // 57296
#define SMEM_BYTES (SM_FLOATS * 4)          // 229184

__global__ void __launch_bounds__(512, 1) scan_kernel(
    float* __restrict__ out, const float* __restrict__ act_seq,
    const float* __restrict__ eps,
    const float* __restrict__ b_ih, const float* __restrict__ b_hh,
    const float* __restrict__ post_W1, const float* __restrict__ post_W2,
    const float* __restrict__ post_b2)
{
    extern __shared__ float sm[];
    float* wgru = sm + SM_WGRU;
    float* w1hs = sm + SM_W1H;   // [jl][k] stride 260
    float* w2s  = sm + SM_W2;    // [k][o] 256x64
    float* b2s  = sm + SM_B2;
    float* xs   = sm + SM_XS;    // [16][308]: h(256) z(32) a(16); reused as hs in BC
    float* hst  = sm + SM_HST;   // [16][17]
    float* o64s = sm + SM_O64;   // [16][64]
    float* stg  = sm + SM_STG;   // [16][96] pm/ps/z staging (jt==0 only)
    float* ebuf = sm + SM_EBUF;  // [512] eps prefetch
    float* abuf = sm + SM_ABUF;  // [256] act prefetch
    float* gtmp = sm + SM_GT;    // [16*16][4] gate exchange
    float* obuf = sm + SM_OB;    // [256] oproj for this step

    const int tid = threadIdx.x;
    const int c   = blockIdx.x;
    const int jt  = c & 15;
    const int bt  = c >> 4;
    const int q   = tid >> 8;          // 0: input gates / K-low ; 1: hidden gates / K-high
    const int jl  = (tid >> 4) & 15;
    const int bl  = tid & 15;
    const int jc  = jt * 16 + jl;
    unsigned* cnt = &g_cnts[bt * 32];

    // ---- preload weights into SMEM (once) ----
    for (int idx = tid; idx < 16 * 1680; idx += 512) {
        int j_ = idx / 1680, r = idx - j_ * 1680;
        int j = jt * 16 + j_;
        float v;
        if (r < 912) { int g = r / 304, k = r - g * 304; v = g_WihT[(size_t)(g * 256 + j) * 304 + k]; }
        else { int r2 = r - 912; int g = r2 >> 8, k = r2 & 255; v = g_WhhT[(size_t)(g * 256 + j) * 256 + k]; }
        wgru[idx] = v;
    }
    for (int idx = tid; idx < 16 * 256; idx += 512) {
        int j_ = idx >> 8, k = idx & 255;
        w1hs[j_ * 260 + k] = post_W1[(size_t)k * 256 + jt * 16 + j_];
    }
    for (int idx = tid; idx < 16384; idx += 512) w2s[idx] = post_W2[idx];
    if (tid < 64) b2s[tid] = post_b2[tid];
    __syncthreads();

    // per-thread biases for this q's gates
    const float bg0 = q ? b_hh[jc]       : b_ih[jc];
    const float bg1 = q ? b_hh[jc + 256] : b_ih[jc + 256];
    const float bg2 = q ? b_hh[jc + 512] : b_ih[jc + 512];

    unsigned barv = 0;

    for (int t = 0; t < T_STEPS; t++) {
        // oproj prefetch into smem (consumed by phase BC)
        if (tid < 256) {
            int b_l = tid >> 4, j_l = tid & 15;
            obuf[tid] = g_oproj[((size_t)(bt * 16 + b_l) * T_STEPS + t) * 256 + jt * 16 + j_l];
        }

        // ========== Phase A ==========
        if (t == 0) {
            if (tid < 256) {
                int b_l = tid >> 4, j_l = tid & 15;
                g_state[(bt * 16 + b_l) * 256 + jt * 16 + j_l] = 0.f;
            }
            __syncthreads();
            barv += 16; bar_arrive(cnt);
            if (tid < 256) {
                int b_l = tid >> 4, j_l = tid & 15;
                out[((size_t)(bt * 16 + b_l) * T_STEPS + 0) * OUT_D + jt * 16 + j_l] = 0.f;
            }
            bar_wait(cnt, barv);
        } else {
            // --- (a) split loads: tid<256 o64 reduce; tid>=256 h + act into xs ---
            if (tid < 256) {
                int b_l = tid >> 4, og = (tid & 15) * 4;
                float4 racc = *(const float4*)(b2s + og);
#pragma unroll
                for (int qq = 0; qq < 16; qq++) {
                    float4 v = ldcg4(g_part + ((size_t)(bt * 16 + b_l) * 16 + qq) * 64 + og);
                    racc.x += v.x; racc.y += v.y; racc.z += v.z; racc.w += v.w;
                }
                *(float4*)(o64s + b_l * 64 + og) = racc;
            } else {
                int tid2 = tid - 256;
#pragma unroll
                for (int p = 0; p < 4; p++) {
                    int idx = tid2 + p * 256;          // 0..1023 float4 slots
                    int b_l = idx >> 6, k4 = idx & 63;
                    float4 v = ldcg4(g_state + (bt * 16 + b_l) * 256 + k4 * 4);
                    *(float4*)(xs + b_l * 308 + k4 * 4) = v;
                }
                int b_l = tid2 >> 4, k = tid2 & 15;
                xs[b_l * 308 + 288 + k] = abuf[tid2];
            }
            __syncthreads();
            // --- (b) sample z_{t-1} (one slot per thread), stage outputs ---
            {
                int b_l = tid >> 5, s = tid & 31;
                float pm = o64s[b_l * 64 + s];
                float ps = softplusf_(o64s[b_l * 64 + 32 + s]) + 0.1f;
                float e  = ebuf[b_l * 32 + s];
                float z  = fmaf(ps, e, pm);
                xs[b_l * 308 + 256 + s] = z;
                if (jt == 0) {
                    stg[b_l * 96 + s]      = pm;
                    stg[b_l * 96 + 32 + s] = ps;
                    stg[b_l * 96 + 64 + s] = z;
                }
            }
            __syncthreads();

            // --- (c) GRU, gate-split ---
            const ulonglong2* xv = (const ulonglong2*)(xs + bl * 308);
            float s0, s1, s2;
            if (q == 0) {
                const ulonglong2* w0 = (const ulonglong2*)(wgru + jl * 1680);
                const ulonglong2* w1 = (const ulonglong2*)(wgru + jl * 1680 + 304);
                const ulonglong2* w2 = (const ulonglong2*)(wgru + jl * 1680 + 608);
                ull a0=0, a1=0, b0=0, b1=0, c0=0, c1=0;
#pragma unroll 4
                for (int k4 = 0; k4 < 76; k4++) {
                    ulonglong2 x2 = xv[k4];
                    ulonglong2 w;
                    w = w0[k4]; fma2(a0, x2.x, w.x); fma2(a1, x2.y, w.y);
                    w = w1[k4]; fma2(b0, x2.x, w.x); fma2(b1, x2.y, w.y);
                    w = w2[k4]; fma2(c0, x2.x, w.x); fma2(c1, x2.y, w.y);
                }
                add2(a0, a1); add2(b0, b1); add2(c0, c1);
                float2 fa = unpack2(a0), fb = unpack2(b0), fc = unpack2(c0);
                s0 = fa.x + fa.y + bg0;
                s1 = fb.x + fb.y + bg1;
                s2 = fc.x + fc.y + bg2;
                int gb = (bl * 16 + jl) * 4;
                gtmp[gb + 0] = s0;
                gtmp[gb + 1] = s1;
                gtmp[gb + 2] = s2;
            } else {
                const ulonglong2* w0 = (const ulonglong2*)(wgru + jl * 1680 + 912);
                const ulonglong2* w1 = (const ulonglong2*)(wgru + jl * 1680 + 1168);
                const ulonglong2* w2 = (const ulonglong2*)(wgru + jl * 1680 + 1424);
                ull a0=0, a1=0, b0=0, b1=0, c0=0, c1=0;
#pragma unroll 4
                for (int k4 = 0; k4 < 64; k4++) {
                    ulonglong2 x2 = xv[k4];
                    ulonglong2 w;
                    w = w0[k4]; fma2(a0, x2.x, w.x); fma2(a1, x2.y, w.y);
                    w = w1[k4]; fma2(b0, x2.x, w.x); fma2(b1, x2.y, w.y);
                    w = w2[k4]; fma2(c0, x2.x, w.x); fma2(c1, x2.y, w.y);
                }
                add2(a0, a1); add2(b0, b1); add2(c0, c1);
                float2 fa = unpack2(a0), fb = unpack2(b0), fc = unpack2(c0);
                s0 = fa.x + fa.y + bg0;
                s1 = fb.x + fb.y + bg1;
                s2 = fc.x + fc.y + bg2;
            }
            __syncthreads();
            if (q == 1) {
                int gb = (bl * 16 + jl) * 4;
                float sir = gtmp[gb + 0], siz = gtmp[gb + 1], sin_ = gtmp[gb + 2];
                float r  = sigmoidf_(sir + s0);
                float zg = sigmoidf_(siz + s1);
                float n  = tanhf(sin_ + r * s2);
                float hprev = xs[bl * 308 + jc];
                hst[bl * 17 + jl] = (1.f - zg) * n + zg * hprev;
            }
            __syncthreads();
            // --- (d) coalesced g_state write ---
            if (tid < 256) {
                int b_l = tid >> 4, j_l = tid & 15;
                g_state[(bt * 16 + b_l) * 256 + jt * 16 + j_l] = hst[b_l * 17 + j_l];
            }
            __syncthreads();
            barv += 16; bar_arrive(cnt);
            // --- (e) deferred out writes, overlapped with barrier poll ---
            if (tid < 256) {
                int b_l = tid >> 4, j_l = tid & 15;
                out[((size_t)(bt * 16 + b_l) * T_STEPS + t) * OUT_D + jt * 16 + j_l] =
                    hst[b_l * 17 + j_l];
            }
            if (jt == 0) {
                int b_l = tid >> 5, s = tid & 31;
                size_t base = ((size_t)(bt * 16 + b_l) * T_STEPS + (t - 1)) * OUT_D;
                out[base + 352 + s] = stg[b_l * 96 + s];
                out[base + 384 + s] = stg[b_l * 96 + 32 + s];
                out[base + 256 + s] = stg[b_l * 96 + 64 + s];
            }
            bar_wait(cnt, barv);
        }

        // ========== Phase BC: hid slice + partial o64 ==========
        {
            float* hs = xs;   // [16][308] reused, only h(256) part
#pragma unroll
            for (int p = 0; p < 2; p++) {
                int idx = tid + p * 512;               // 0..1023 float4 slots
                int b_l = idx >> 6, k4 = idx & 63;
                float4 v = ldcg4(g_state + (bt * 16 + b_l) * 256 + k4 * 4);
                *(float4*)(hs + b_l * 308 + k4 * 4) = v;
            }
            __syncthreads();
            // hid partials: K split by q (128 floats each)
            {
                const ulonglong2* hv2 = (const ulonglong2*)(hs + bl * 308) + q * 32;
                const ulonglong2* wv2 = (const ulonglong2*)(w1hs + jl * 260) + q * 32;
                ull a0 = 0, a1 = 0;
#pragma unroll 8
                for (int k4 = 0; k4 < 32; k4++) {
                    ulonglong2 h2 = hv2[k4], w2v = wv2[k4];
                    fma2(a0, h2.x, w2v.x);
                    fma2(a1, h2.y, w2v.y);
                }
                add2(a0, a1);
                float2 f = unpack2(a0);
                gtmp[(bl * 16 + jl) * 2 + q] = f.x + f.y;
            }
            __syncthreads();
            if (tid < 256) {
                int b_l = tid >> 4, j_l = tid & 15;
                int gb = (b_l * 16 + j_l) * 2;
                float hid = gtmp[gb] + gtmp[gb + 1] + obuf[tid];
                hst[b_l * 17 + j_l] = fmaxf(hid, 0.f);
            }
            __syncthreads();
            // partial o64: rank-16 update with W2 rows [jt*16, jt*16+16), 2 rows/thread
            {
                const int o = tid & 63, bh = tid >> 6;   // bh 0..7
#pragma unroll
                for (int bb = 0; bb < 2; bb++) {
                    int b_l = bh * 2 + bb;
                    float pacc = 0.f;
#pragma unroll
                    for (int k = 0; k < 16; k++)
                        pacc = fmaf(hst[b_l * 17 + k], w2s[(jt * 16 + k) * 64 + o], pacc);
                    g_part[((size_t)(bt * 16 + b_l) * 16 + jt) * 64 + o] = pacc;
                }
            }
            __syncthreads();
            barv += 16; bar_arrive(cnt);
            // --- prefetch next step's eps/act, overlapped with poll ---
            {
                int b_l = tid >> 5, s = tid & 31;
                ebuf[tid] = eps[((size_t)t * B_SZ + bt * 16 + b_l) * 32 + s];
                if (tid < 256)
                    abuf[tid] = act_seq[((size_t)(bt * 16 + (tid >> 4)) * T_STEPS + t) * 16 + (tid & 15)];
            }
            bar_wait(cnt, barv);
        }
    }

    // ========== epilogue: reduce partials for t=511, write outputs ==========
    {
        const int b = c;                       // one batch row per CTA (same bt-group)
        if (tid < 64) {
            float acc = b2s[tid];
#pragma unroll
            for (int qq = 0; qq < 16; qq++)
                acc += ldcg1(g_part + ((size_t)b * 16 + qq) * 64 + tid);
            o64s[tid] = acc;
        }
        __syncthreads();
        if (tid < 32) {
            int s = tid;
            float pm = o64s[s];
            float ps = softplusf_(o64s[32 + s]) + 0.1f;
            float e  = eps[((size_t)(T_STEPS - 1) * B_SZ + b) * 32 + s];
            float z  = fmaf(ps, e, pm);
            size_t base = ((size_t)b * T_STEPS + (T_STEPS - 1)) * OUT_D;
            out[base + 352 + s] = pm;
            out[base + 384 + s] = ps;
            out[base + 256 + s] = z;
        }
    }
}

// ---------------- fp32 tiled GEMM with f32x2 (R6 version): C = act(A@W + bias) ----------------
__global__ void gemm_kernel(int M, int N, int K,
                            const float* __restrict__ A, int lda,
                            const float* __restrict__ W,
                            const float* __restrict__ bias,
                            float* __restrict__ C, int ldc, int act)
{
    __shared__ __align__(16) float As[16][132];
    __shared__ __align__(16) float Ws[16][64];
    const int tid = threadIdx.x;
    const int tx = tid & 15;
    const int ty = tid >> 4;
    const int rowBase = blockIdx.y * 128;
    const int colBase = blockIdx.x * 64;

    ull acc2[4][4];
#pragma unroll
    for (int p = 0; p < 4; p++)
#pragma unroll
        for (int j = 0; j < 4; j++) acc2[p][j] = 0ull;

    const int ka = tid & 15;
    const int ra = tid >> 4;
    const int nw = tid & 63;
    const int kw = tid >> 6;

    for (int k0 = 0; k0 < K; k0 += 16) {
#pragma unroll
        for (int p = 0; p < 8; p++)
            As[ka][ra + p * 16] = A[(size_t)(rowBase + ra + p * 16) * lda + k0 + ka];
#pragma unroll
        for (int p = 0; p < 4; p++)
            Ws[kw + p * 4][nw] = W[(size_t)(k0 + kw + p * 4) * N + colBase + nw];
        __syncthreads();
#pragma unroll
        for (int k = 0; k < 16; k++) {
            ulonglong2 A01 = *(const ulonglong2*)&As[k][ty * 8];
            ulonglong2 A23 = *(const ulonglong2*)&As[k][ty * 8 + 4];
            float4 wv = *(const float4*)&Ws[k][tx * 4];
            ull wd0 = pack2(wv.x, wv.x), wd1 = pack2(wv.y, wv.y);
            ull wd2 = pack2(wv.z, wv.z), wd3 = pack2(wv.w, wv.w);
            fma2(acc2[0][0], A01.x, wd0); fma2(acc2[0][1], A01.x, wd1);
            fma2(acc2[0][2], A01.x, wd2); fma2(acc2[0][3], A01.x, wd3);
            fma2(acc2[1][0], A01.y, wd0); fma2(acc2[1][1], A01.y, wd1);
            fma2(acc2[1][2], A01.y, wd2); fma2(acc2[1][3], A01.y, wd3);
            fma2(acc2[2][0], A23.x, wd0); fma2(acc2[2][1], A23.x, wd1);
            fma2(acc2[2][2], A23.x, wd2); fma2(acc2[2][3], A23.x, wd3);
            fma2(acc2[3][0], A23.y, wd0); fma2(acc2[3][1], A23.y, wd1);
            fma2(acc2[3][2], A23.y, wd2); fma2(acc2[3][3], A23.y, wd3);
        }
        __syncthreads();
    }
#pragma unroll
    for (int p = 0; p < 4; p++) {
#pragma unroll
        for (int j = 0; j < 4; j++) {
            float2 f = unpack2(acc2[p][j]);
            int cc = colBase + tx * 4 + j;
            float bval = bias ? bias[cc] : 0.f;
            float v0 = f.x + bval;
            float v1 = f.y + bval;
            if (act == 1) { v0 = fmaxf(v0, 0.f); v1 = fmaxf(v1, 0.f); }
            else if (act == 2 && cc >= 32) {
                v0 = softplusf_(v0) + 0.1f;
                v1 = softplusf_(v1) + 0.1f;
            }
            int r0 = rowBase + ty * 8 + 2 * p;
            C[(size_t)r0 * ldc + cc] = v0;
            C[(size_t)(r0 + 1) * ldc + cc] = v1;
        }
    }
}

// ---------------- GEMV (N=1): K=256 ----------------
__global__ void gemv_kernel(const float* __restrict__ A, int lda,
                            const float* __restrict__ w,
                            const float* __restrict__ bias, float* __restrict__ C, int act)
{
    const int warp = threadIdx.x >> 5, lane = threadIdx.x & 31;
    const int row = blockIdx.x * 8 + warp;
    const float* a = A + (size_t)row * lda;
    float acc = 0.f;
#pragma unroll
    for (int i = 0; i < 8; i++) acc = fmaf(a[lane + 32 * i], w[lane + 32 * i], acc);
#pragma unroll
    for (int off = 16; off; off >>= 1) acc += __shfl_xor_sync(0xffffffffu, acc, off);
    if (lane == 0) {
        float v = acc + bias[0];
        if (act == 3) v = sigmoidf_(v);
        C[(size_t)row * OUT_D] = v;
    }
}

// ---------------- driver ----------------
extern "C" void kernel_launch(void* const* d_in, const int* in_sizes, int n_in,
                              void* d_out, int out_size)
{
    const float* obs      = (const float*)d_in[0];
    const float* act      = (const float*)d_in[1];
    const float* eps      = (const float*)d_in[2];
    const float* prior_W1 = (const float*)d_in[3];
    const float* prior_b1 = (const float*)d_in[4];
    const float* prior_W2 = (const float*)d_in[5];
    const float* prior_b2 = (const float*)d_in[6];
    const float* post_W1  = (const float*)d_in[7];
    const float* post_b1  = (const float*)d_in[8];
    const float* post_W2  = (const float*)d_in[9];
    const float* post_b2  = (const float*)d_in[10];
    const float* W_ih     = (const float*)d_in[11];
    const float* b_ih     = (const float*)d_in[12];
    const float* W_hh     = (const float*)d_in[13];
    const float* b_hh     = (const float*)d_in[14];
    const float* dobs_W1  = (const float*)d_in[15];
    const float* dobs_b1  = (const float*)d_in[16];
    const float* dobs_W2  = (const float*)d_in[17];
    const float* dobs_b2  = (const float*)d_in[18];
    const float* drew_W1  = (const float*)d_in[19];
    const float* drew_b1  = (const float*)d_in[20];
    const float* drew_W2  = (const float*)d_in[21];
    const float* drew_b2  = (const float*)d_in[22];
    const float* dcont_W1 = (const float*)d_in[23];
    const float* dcont_b1 = (const float*)d_in[24];
    const float* dcont_W2 = (const float*)d_in[25];
    const float* dcont_b2 = (const float*)d_in[26];
    float* out = (float*)d_out;

    float *oproj_p = nullptr, *hid3_p = nullptr, *wcat_p = nullptr, *bcat_p = nullptr;
    cudaGetSymbolAddress((void**)&oproj_p, g_oproj);
    cudaGetSymbolAddress((void**)&hid3_p, g_hid3);
    cudaGetSymbolAddress((void**)&wcat_p, g_Wcat);
    cudaGetSymbolAddress((void**)&bcat_p, g_bcat);

    static int attrs_set = 0;
    if (!attrs_set) {
        cudaFuncSetAttribute(scan_kernel, cudaFuncAttributeMaxDynamicSharedMemorySize, SMEM_BYTES);
        attrs_set = 1;
    }

    prep_kernel<<<1680, 256>>>(W_ih, W_hh);
    prep2_kernel<<<1152, 256>>>(prior_W1, prior_b1, dobs_W1, dobs_b1,
                                drew_W1, drew_b1, dcont_W1, dcont_b1);

    // Phase A: o_proj = obs @ W1o + post_b1  (rows 256..1279 of post_W1)
    gemm_kernel<<<dim3(4, BT / 128), 256>>>(BT, 256, 1024, obs, 1024,
                                            post_W1 + 256 * 256, post_b1,
                                            oproj_p, 256, 0);

    // Phase B: persistent sequential scan (GRU + posterior + sample)
    scan_kernel<<<NCTA, 512, SMEM_BYTES>>>(out, act, eps, b_ih, b_hh,
                                           post_W1, post_W2, post_b2);

    // Phase C: merged decoder/prior L1: hid3 = relu([h,z] @ Wcat + bcat)
    gemm_kernel<<<dim3(16, BT / 128), 256>>>(BT, 1024, 288, out, OUT_D,
                                             wcat_p, bcat_p, hid3_p, 1024, 1);
    // prior L2 (cols 0..255 of hid3)
    gemm_kernel<<<dim3(1, BT / 128), 256>>>(BT, 64, 256, hid3_p, 1024,
                                            prior_W2, prior_b2, out + 288, OUT_D, 2);
    // obs decoder L2 (cols 256..511)
    gemm_kernel<<<dim3(16, BT / 128), 256>>>(BT, 1024, 256, hid3_p + 256, 1024,
                                             dobs_W2, dobs_b2, out + 416, OUT_D, 0);
    // reward (cols 512..767) / continuation (cols 768..1023)
    gemv_kernel<<<BT / 8, 256>>>(hid3_p + 512, 1024, drew_W2, drew_b2, out + 1440, 0);
    gemv_kernel<<<BT / 8, 256>>>(hid3_p + 768, 1024, dcont_W2, dcont_b2, out + 1441, 3);
}

// round 13
// speedup vs baseline: 1.2436x; 1.2436x over previous
#include <cuda_runtime.h>
#include <cuda_bf16.h>
#include <cstdint>
#include <math.h>

#define T_STEPS 512
#define B_SZ    128
#define BT      (B_SZ * T_STEPS)
#define OUT_D   1442
#define NCTA    128

typedef unsigned long long ull;

// ---------------- scratch (static device globals; no allocation) ----------------
__device__ __align__(16) float g_oproj[BT * 256];          // obs @ W1o + post_b1, [B][T][256]
__device__ __align__(16) float g_hid3 [(size_t)BT * 1024]; // merged decoder hidden
__device__ __align__(16) float g_WihT [768 * 304];         // W_ih transposed: [n][k]
__device__ __align__(16) float g_WhhT [768 * 256];         // W_hh transposed: [n][k]
__device__ __align__(16) float g_bcat [1024];
__device__ __align__(16) float g_part [B_SZ * 16 * 64];    // partial o64: [b][jt][64]
__device__ __align__(16) float g_state[B_SZ * 256];        // h only
__device__ unsigned g_cnts[8 * 32];                        // per-group barrier counters

// bf16-split weights in [k][n] layout (hi + lo)
__device__ __align__(16) __nv_bfloat16 g_Wo_hi[1024 * 256], g_Wo_lo[1024 * 256];   // oproj  (K=1024,N=256)
__device__ __align__(16) __nv_bfloat16 g_Wc_hi[320 * 1024], g_Wc_lo[320 * 1024];   // Wcat   (K=320, N=1024)
__device__ __align__(16) __nv_bfloat16 g_Wd_hi[256 * 1024], g_Wd_lo[256 * 1024];   // dobsW2 (K=256, N=1024)
__device__ __align__(16) __nv_bfloat16 g_Wp_hi[256 * 64],   g_Wp_lo[256 * 64];     // priorW2(K=256, N=64)

__device__ __forceinline__ float sigmoidf_(float x) { return 1.f / (1.f + expf(-x)); }
__device__ __forceinline__ float softplusf_(float x) {
    return fmaxf(x, 0.f) + log1pf(expf(-fabsf(x)));
}

// packed fp32x2 helpers
__device__ __forceinline__ void fma2(ull& d, ull a, ull b) {
    asm("fma.rn.f32x2 %0, %1, %2, %0;" : "+l"(d) : "l"(a), "l"(b));
}
__device__ __forceinline__ void add2(ull& d, ull a) {
    asm("add.rn.f32x2 %0, %0, %1;" : "+l"(d) : "l"(a));
}
__device__ __forceinline__ float2 unpack2(ull v) {
    float2 f; asm("mov.b64 {%0, %1}, %2;" : "=f"(f.x), "=f"(f.y) : "l"(v)); return f;
}

// L2-direct loads
__device__ __forceinline__ float4 ldcg4(const float* p) {
    float4 v;
    asm volatile("ld.global.cg.v4.f32 {%0,%1,%2,%3}, [%4];"
                 : "=f"(v.x), "=f"(v.y), "=f"(v.z), "=f"(v.w) : "l"(p));
    return v;
}
__device__ __forceinline__ float ldcg1(const float* p) {
    float v;
    asm volatile("ld.global.cg.f32 %0, [%1];" : "=f"(v) : "l"(p));
    return v;
}

// scoped-atomic barrier primitives (no MEMBAR.GL)
__device__ __forceinline__ void bar_arrive(unsigned* cnt) {
    if (threadIdx.x == 0)
        asm volatile("red.release.gpu.global.add.u32 [%0], %1;" :: "l"(cnt), "r"(1u) : "memory");
}
__device__ __forceinline__ void bar_wait(unsigned* cnt, unsigned target) {
    if (threadIdx.x == 0) {
        unsigned v;
        do {
            asm volatile("ld.acquire.gpu.global.u32 %0, [%1];" : "=r"(v) : "l"(cnt) : "memory");
        } while (v < target);
    }
    __syncthreads();
}

// ---------------- mma.sync helpers (sm_80+ path, works on plain sm_103) ----------------
__device__ __forceinline__ uint32_t smem_u32(const void* p) {
    uint32_t a;
    asm("{ .reg .u64 t; cvta.to.shared.u64 t, %1; cvt.u32.u64 %0, t; }" : "=r"(a) : "l"(p));
    return a;
}
__device__ __forceinline__ void ldsm4(uint32_t* r, uint32_t addr) {
    asm volatile("ldmatrix.sync.aligned.m8n8.x4.shared.b16 {%0,%1,%2,%3}, [%4];"
                 : "=r"(r[0]), "=r"(r[1]), "=r"(r[2]), "=r"(r[3]) : "r"(addr));
}
__device__ __forceinline__ void ldsm4t(uint32_t* r, uint32_t addr) {
    asm volatile("ldmatrix.sync.aligned.m8n8.x4.trans.shared.b16 {%0,%1,%2,%3}, [%4];"
                 : "=r"(r[0]), "=r"(r[1]), "=r"(r[2]), "=r"(r[3]) : "r"(addr));
}
__device__ __forceinline__ void mma16816(float* c, const uint32_t* a, uint32_t b0, uint32_t b1) {
    asm volatile("mma.sync.aligned.m16n8k16.row.col.f32.bf16.bf16.f32 "
                 "{%0,%1,%2,%3}, {%4,%5,%6,%7}, {%8,%9}, {%0,%1,%2,%3};"
                 : "+f"(c[0]), "+f"(c[1]), "+f"(c[2]), "+f"(c[3])
                 : "r"(a[0]), "r"(a[1]), "r"(a[2]), "r"(a[3]), "r"(b0), "r"(b1));
}

// ---------------- prep: transpose GRU weights, reset barriers ----------------
__global__ void prep_kernel(const float* __restrict__ W_ih, const float* __restrict__ W_hh) {
    if (blockIdx.x == 0 && threadIdx.x < 8) g_cnts[threadIdx.x * 32] = 0u;
    int idx = blockIdx.x * 256 + threadIdx.x;
    const int n1 = 768 * 304;
    if (idx < n1) {
        int n = idx / 304, k = idx - n * 304;
        g_WihT[idx] = W_ih[k * 768 + n];
    } else {
        int r = idx - n1;
        int n = r >> 8, k = r & 255;
        g_WhhT[r] = W_hh[k * 768 + n];
    }
}

// bias concat for Wcat
__global__ void prep2_kernel(const float* __restrict__ prior_b1, const float* __restrict__ dobs_b1,
                             const float* __restrict__ drew_b1,  const float* __restrict__ dcont_b1)
{
    int j = blockIdx.x * 256 + threadIdx.x;        // 1024
    int g = j >> 8, jj = j & 255;
    float b;
    if (g == 0)      b = prior_b1[jj];
    else if (g == 1) b = dobs_b1[jj];
    else if (g == 2) b = drew_b1[jj];
    else             b = dcont_b1[jj];
    g_bcat[j] = b;
}

// build bf16-split weights, [k][n] layout
__global__ void prep3_kernel(const float* __restrict__ post_W1,
                             const float* __restrict__ prior_W1, const float* __restrict__ dobs_W1,
                             const float* __restrict__ drew_W1,  const float* __restrict__ dcont_W1,
                             const float* __restrict__ dobs_W2,  const float* __restrict__ prior_W2)
{
    const int No = 1024 * 256, Nc = 320 * 1024, Nd = 256 * 1024;
    int idx = blockIdx.x * 256 + threadIdx.x;
    float w; __nv_bfloat16* hi; __nv_bfloat16* lo; int off;
    if (idx < No) {
        int k = idx >> 8, n = idx & 255;
        w = post_W1[(size_t)(256 + k) * 256 + n];
        hi = g_Wo_hi; lo = g_Wo_lo; off = idx;
    } else if (idx < No + Nc) {
        int r = idx - No;
        int k = r >> 10, n = r & 1023;
        int g = n >> 8, j = n & 255;
        if (k >= 288) w = 0.f;
        else if (g == 0) w = (k < 256) ? prior_W1[k * 256 + j] : 0.f;
        else if (g == 1) w = dobs_W1[(size_t)k * 256 + j];
        else if (g == 2) w = drew_W1[(size_t)k * 256 + j];
        else             w = dcont_W1[(size_t)k * 256 + j];
        hi = g_Wc_hi; lo = g_Wc_lo; off = r;
    } else if (idx < No + Nc + Nd) {
        int r = idx - No - Nc;
        w = dobs_W2[r];                       // already [k][n]
        hi = g_Wd_hi; lo = g_Wd_lo; off = r;
    } else {
        int r = idx - No - Nc - Nd;
        w = prior_W2[r];                      // already [k][n]
        hi = g_Wp_hi; lo = g_Wp_lo; off = r;
    }
    __nv_bfloat16 h = __float2bfloat16(w);
    hi[off] = h;
    lo[off] = __float2bfloat16(w - __bfloat162float(h));
}

// ---------------- split-bf16 tensor GEMM via mma.sync (tile 128x64, K chunks of 32) ----------------
// C = act(A @ (W_hi + W_lo) + bias); W stored [k][n].
#define AP 40   // A smem row stride (bf16)
#define BP 72   // B smem row stride (bf16)

__global__ void __launch_bounds__(256) mmagemm_kernel(
    int K, int Aklim, const float* __restrict__ A, int lda,
    const __nv_bfloat16* __restrict__ Whi, const __nv_bfloat16* __restrict__ Wlo, int ldw,
    const float* __restrict__ bias, float* __restrict__ C, int ldc, int act)
{
    __shared__ __align__(16) __nv_bfloat16 Ahi[128 * AP], Alo[128 * AP];
    __shared__ __align__(16) __nv_bfloat16 Bhi[32 * BP],  Blo[32 * BP];

    const int tid = threadIdx.x, lane = tid & 31, wid = tid >> 5;
    const int warp_m = wid & 3, warp_n = wid >> 2;       // 4 x 2 warp grid
    const int rowBase = blockIdx.y * 128, colBase = blockIdx.x * 64;

    float acc[2][4][4];
#pragma unroll
    for (int mt = 0; mt < 2; mt++)
#pragma unroll
        for (int nt = 0; nt < 4; nt++)
#pragma unroll
            for (int i = 0; i < 4; i++) acc[mt][nt][i] = 0.f;

    const uint32_t aHiB = smem_u32(Ahi), aLoB = smem_u32(Alo);
    const uint32_t bHiB = smem_u32(Bhi), bLoB = smem_u32(Blo);

    for (int kk = 0; kk < K; kk += 32) {
        // ---- stage A: 128 rows x 32 k, fp32 -> bf16 hi/lo ----
        {
            const int r = tid >> 1, kh = (tid & 1) * 16;
            const float* arow = A + (size_t)(rowBase + r) * lda + kk + kh;
            float x[16];
#pragma unroll
            for (int j = 0; j < 8; j++) {
                float2 v = *(const float2*)(arow + 2 * j);
                x[2 * j] = v.x; x[2 * j + 1] = v.y;
            }
#pragma unroll
            for (int j = 0; j < 16; j++)
                if (kk + kh + j >= Aklim) x[j] = 0.f;
            uint32_t hw[8], lw[8];
#pragma unroll
            for (int j = 0; j < 8; j++) {
                __nv_bfloat16 h0 = __float2bfloat16(x[2 * j]);
                __nv_bfloat16 h1 = __float2bfloat16(x[2 * j + 1]);
                __nv_bfloat16 l0 = __float2bfloat16(x[2 * j]     - __bfloat162float(h0));
                __nv_bfloat16 l1 = __float2bfloat16(x[2 * j + 1] - __bfloat162float(h1));
                hw[j] = (uint32_t)__bfloat16_as_ushort(h0) | ((uint32_t)__bfloat16_as_ushort(h1) << 16);
                lw[j] = (uint32_t)__bfloat16_as_ushort(l0) | ((uint32_t)__bfloat16_as_ushort(l1) << 16);
            }
            __nv_bfloat16* dh = Ahi + r * AP + kh;
            __nv_bfloat16* dl = Alo + r * AP + kh;
            *(uint4*)dh       = make_uint4(hw[0], hw[1], hw[2], hw[3]);
            *(uint4*)(dh + 8) = make_uint4(hw[4], hw[5], hw[6], hw[7]);
            *(uint4*)dl       = make_uint4(lw[0], lw[1], lw[2], lw[3]);
            *(uint4*)(dl + 8) = make_uint4(lw[4], lw[5], lw[6], lw[7]);
        }
        // ---- stage B: 32 k-rows x 64 n, direct bf16 copy ----
        {
            const int bk = tid >> 3, bn = (tid & 7) * 8;
            size_t src = (size_t)(kk + bk) * ldw + colBase + bn;
            *(uint4*)(Bhi + bk * BP + bn) = *(const uint4*)(Whi + src);
            *(uint4*)(Blo + bk * BP + bn) = *(const uint4*)(Wlo + src);
        }
        __syncthreads();

        // ---- compute: 2 k16 steps ----
#pragma unroll
        for (int k16 = 0; k16 < 32; k16 += 16) {
            uint32_t ah[2][4], al[2][4], bh[2][4], bl[2][4];
#pragma unroll
            for (int mt = 0; mt < 2; mt++) {
                uint32_t off = ((warp_m * 32 + mt * 16 + (lane & 15)) * AP
                                + k16 + ((lane >> 4) << 3)) * 2;
                ldsm4(ah[mt], aHiB + off);
                ldsm4(al[mt], aLoB + off);
            }
#pragma unroll
            for (int np = 0; np < 2; np++) {
                uint32_t off = ((k16 + (lane & 15)) * BP
                                + warp_n * 32 + np * 16 + ((lane >> 4) << 3)) * 2;
                ldsm4t(bh[np], bHiB + off);
                ldsm4t(bl[np], bLoB + off);
            }
#pragma unroll
            for (int mt = 0; mt < 2; mt++)
#pragma unroll
                for (int nt = 0; nt < 4; nt++) {
                    int np = nt >> 1, bi = (nt & 1) * 2;
                    mma16816(acc[mt][nt], ah[mt], bh[np][bi], bh[np][bi + 1]);
                    mma16816(acc[mt][nt], ah[mt], bl[np][bi], bl[np][bi + 1]);
                    mma16816(acc[mt][nt], al[mt], bh[np][bi], bh[np][bi + 1]);
                }
        }
        __syncthreads();
    }

    // ---- epilogue ----
#pragma unroll
    for (int mt = 0; mt < 2; mt++) {
#pragma unroll
        for (int nt = 0; nt < 4; nt++) {
            int row0 = rowBase + warp_m * 32 + mt * 16 + (lane >> 2);
            int col  = colBase + warp_n * 32 + (nt >> 1) * 16 + (nt & 1) * 8 + (lane & 3) * 2;
            float v0 = acc[mt][nt][0], v1 = acc[mt][nt][1];
            float v2 = acc[mt][nt][2], v3 = acc[mt][nt][3];
            if (bias) {
                float b0 = bias[col], b1 = bias[col + 1];
                v0 += b0; v1 += b1; v2 += b0; v3 += b1;
            }
            if (act == 1) {
                v0 = fmaxf(v0, 0.f); v1 = fmaxf(v1, 0.f);
                v2 = fmaxf(v2, 0.f); v3 = fmaxf(v3, 0.f);
            } else if (act == 2) {
                if (col >= 32)     { v0 = softplusf_(v0) + 0.1f; v2 = softplusf_(v2) + 0.1f; }
                if (col + 1 >= 32) { v1 = softplusf_(v1) + 0.1f; v3 = softplusf_(v3) + 0.1f; }
            }
            *(float2*)(C + (size_t)row0 * ldc + col)       = make_float2(v0, v1);
            *(float2*)(C + (size_t)(row0 + 8) * ldc + col) = make_float2(v2, v3);
        }
    }
}

// ---------------- persistent scan kernel (exact R6 structure — best known) ----------------
#define SM_WGRU 0
#define SM_W1H  26880
#define SM_W2   (SM_W1H + 16*260)
#define SM_B2   (SM_W2 + 16384)
#define SM_XS   (SM_B2 + 64)
#define SM_HST  (SM_XS + 16*308)
#define SM_O64  (SM_HST + 16*17)
#define SM_STG  (SM_O64 + 1024)
#define SM_EBUF (SM_STG + 16*96)
#define SM_ABUF (SM_EBUF + 512)
#define SM_FLOATS (SM_ABUF + 256)
#define SMEM_BYTES (SM_FLOATS * 4)

__global__ void __launch_bounds__(256, 1) scan_kernel(
    float* __restrict__ out, const float* __restrict__ act_seq,
    const float* __restrict__ eps,
    const float* __restrict__ b_ih, const float* __restrict__ b_hh,
    const float* __restrict__ post_W1, const float* __restrict__ post_W2,
    const float* __restrict__ post_b2)
{
    extern __shared__ float sm[];
    float* wgru = sm + SM_WGRU;
    float* w1hs = sm + SM_W1H;
    float* w2s  = sm + SM_W2;
    float* b2s  = sm + SM_B2;
    float* xs   = sm + SM_XS;
    float* hst  = sm + SM_HST;
    float* o64s = sm + SM_O64;
    float* stg  = sm + SM_STG;
    float* ebuf = sm + SM_EBUF;
    float* abuf = sm + SM_ABUF;

    const int tid = threadIdx.x;
    const int c   = blockIdx.x;
    const int jt  = c & 15;
    const int bt  = c >> 4;
    const int jl  = tid >> 4;
    const int bl  = tid & 15;
    const int jc  = jt * 16 + jl;
    const int b_a = bt * 16 + bl;
    unsigned* cnt = &g_cnts[bt * 32];

    for (int idx = tid; idx < 16 * 1680; idx += 256) {
        int j_ = idx / 1680, r = idx - j_ * 1680;
        int j = jt * 16 + j_;
        float v;
        if (r < 912) { int g = r / 304, k = r - g * 304; v = g_WihT[(size_t)(g * 256 + j) * 304 + k]; }
        else { int r2 = r - 912; int g = r2 >> 8, k = r2 & 255; v = g_WhhT[(size_t)(g * 256 + j) * 256 + k]; }
        wgru[idx] = v;
    }
    for (int idx = tid; idx < 16 * 256; idx += 256) {
        int j_ = idx >> 8, k = idx & 255;
        w1hs[j_ * 260 + k] = post_W1[(size_t)k * 256 + jt * 16 + j_];
    }
    for (int idx = tid; idx < 16384; idx += 256) w2s[idx] = post_W2[idx];
    if (tid < 64) b2s[tid] = post_b2[tid];
    __syncthreads();

    const float bir = b_ih[jc], biz = b_ih[jc + 256], bin_ = b_ih[jc + 512];
    const float bhr = b_hh[jc], bhz = b_hh[jc + 256], bhn = b_hh[jc + 512];

    unsigned barv = 0;

    for (int t = 0; t < T_STEPS; t++) {
        float oproj_reg = g_oproj[((size_t)b_a * T_STEPS + t) * 256 + jc];

        if (t == 0) {
            int b_l = tid >> 4, j_l = tid & 15;
            g_state[(bt * 16 + b_l) * 256 + jt * 16 + j_l] = 0.f;
            __syncthreads();
            barv += 16; bar_arrive(cnt);
            out[((size_t)(bt * 16 + b_l) * T_STEPS + 0) * OUT_D + jt * 16 + j_l] = 0.f;
            bar_wait(cnt, barv);
        } else {
            int b_l = tid >> 4, og = (tid & 15) * 4;
            float4 racc = *(const float4*)(b2s + og);
#pragma unroll
            for (int q = 0; q < 16; q++) {
                float4 v = ldcg4(g_part + ((size_t)(bt * 16 + b_l) * 16 + q) * 64 + og);
                racc.x += v.x; racc.y += v.y; racc.z += v.z; racc.w += v.w;
            }
            float4 hv[4];
#pragma unroll
            for (int p = 0; p < 4; p++) {
                int idx = tid + p * 256;
                int bl_ = idx >> 6, k4 = idx & 63;
                hv[p] = ldcg4(g_state + (bt * 16 + bl_) * 256 + k4 * 4);
            }
            *(float4*)(o64s + b_l * 64 + og) = racc;
#pragma unroll
            for (int p = 0; p < 4; p++) {
                int idx = tid + p * 256;
                int bl_ = idx >> 6, k4 = idx & 63;
                *(float4*)(xs + bl_ * 308 + k4 * 4) = hv[p];
            }
            xs[(tid >> 4) * 308 + 288 + (tid & 15)] = abuf[tid];
            __syncthreads();
            for (int idx = tid; idx < 512; idx += 256) {
                int bl_ = idx >> 5, s = idx & 31;
                float pm = o64s[bl_ * 64 + s];
                float ps = softplusf_(o64s[bl_ * 64 + 32 + s]) + 0.1f;
                float e  = ebuf[bl_ * 32 + s];
                float z  = fmaf(ps, e, pm);
                xs[bl_ * 308 + 256 + s] = z;
                if (jt == 0) {
                    stg[bl_ * 96 + s]      = pm;
                    stg[bl_ * 96 + 32 + s] = ps;
                    stg[bl_ * 96 + 64 + s] = z;
                }
            }
            __syncthreads();

            const ulonglong2* xv  = (const ulonglong2*)(xs + bl * 308);
            const ulonglong2* wir = (const ulonglong2*)(wgru + jl * 1680);
            const ulonglong2* wiz = (const ulonglong2*)(wgru + jl * 1680 + 304);
            const ulonglong2* win = (const ulonglong2*)(wgru + jl * 1680 + 608);
            const ulonglong2* whr = (const ulonglong2*)(wgru + jl * 1680 + 912);
            const ulonglong2* whz = (const ulonglong2*)(wgru + jl * 1680 + 1168);
            const ulonglong2* whn = (const ulonglong2*)(wgru + jl * 1680 + 1424);

            ull air0=0, air1=0, aiz0=0, aiz1=0, ain0=0, ain1=0;
            ull ahr0=0, ahr1=0, ahz0=0, ahz1=0, ahn0=0, ahn1=0;
#pragma unroll 4
            for (int k4 = 0; k4 < 64; k4++) {
                ulonglong2 x2 = xv[k4];
                ulonglong2 w;
                w = wir[k4]; fma2(air0, x2.x, w.x); fma2(air1, x2.y, w.y);
                w = wiz[k4]; fma2(aiz0, x2.x, w.x); fma2(aiz1, x2.y, w.y);
                w = win[k4]; fma2(ain0, x2.x, w.x); fma2(ain1, x2.y, w.y);
                w = whr[k4]; fma2(ahr0, x2.x, w.x); fma2(ahr1, x2.y, w.y);
                w = whz[k4]; fma2(ahz0, x2.x, w.x); fma2(ahz1, x2.y, w.y);
                w = whn[k4]; fma2(ahn0, x2.x, w.x); fma2(ahn1, x2.y, w.y);
            }
#pragma unroll
            for (int k4 = 64; k4 < 76; k4++) {
                ulonglong2 x2 = xv[k4];
                ulonglong2 w;
                w = wir[k4]; fma2(air0, x2.x, w.x); fma2(air1, x2.y, w.y);
                w = wiz[k4]; fma2(aiz0, x2.x, w.x); fma2(aiz1, x2.y, w.y);
                w = win[k4]; fma2(ain0, x2.x, w.x); fma2(ain1, x2.y, w.y);
            }
            add2(air0, air1); add2(aiz0, aiz1); add2(ain0, ain1);
            add2(ahr0, ahr1); add2(ahz0, ahz1); add2(ahn0, ahn1);
            float2 fr = unpack2(air0), fz = unpack2(aiz0), fn = unpack2(ain0);
            float2 gr = unpack2(ahr0), gz = unpack2(ahz0), gn = unpack2(ahn0);
            float sir = fr.x + fr.y + bir;
            float siz = fz.x + fz.y + biz;
            float sin_= fn.x + fn.y + bin_;
            float shr = gr.x + gr.y + bhr;
            float shz = gz.x + gz.y + bhz;
            float shn = gn.x + gn.y + bhn;

            float r  = sigmoidf_(sir + shr);
            float zg = sigmoidf_(siz + shz);
            float n  = tanhf(sin_ + r * shn);
            float hprev = xs[bl * 308 + jc];
            float hnew  = (1.f - zg) * n + zg * hprev;
            hst[bl * 17 + jl] = hnew;
            __syncthreads();
            {
                int b_l2 = tid >> 4, j_l = tid & 15;
                g_state[(bt * 16 + b_l2) * 256 + jt * 16 + j_l] = hst[b_l2 * 17 + j_l];
            }
            __syncthreads();
            barv += 16; bar_arrive(cnt);
            {
                int b_l2 = tid >> 4, j_l = tid & 15;
                out[((size_t)(bt * 16 + b_l2) * T_STEPS + t) * OUT_D + jt * 16 + j_l] =
                    hst[b_l2 * 17 + j_l];
            }
            if (jt == 0) {
                for (int idx = tid; idx < 512; idx += 256) {
                    int bl_ = idx >> 5, s = idx & 31;
                    size_t base = ((size_t)(bt * 16 + bl_) * T_STEPS + (t - 1)) * OUT_D;
                    out[base + 352 + s] = stg[bl_ * 96 + s];
                    out[base + 384 + s] = stg[bl_ * 96 + 32 + s];
                    out[base + 256 + s] = stg[bl_ * 96 + 64 + s];
                }
            }
            bar_wait(cnt, barv);
        }

        {
            float* hs = xs;
#pragma unroll
            for (int p = 0; p < 4; p++) {
                int idx = tid + p * 256;
                int b_l = idx >> 6, k4 = idx & 63;
                float4 v = ldcg4(g_state + (bt * 16 + b_l) * 256 + k4 * 4);
                *(float4*)(hs + b_l * 260 + k4 * 4) = v;
            }
            __syncthreads();
            const ulonglong2* hv2 = (const ulonglong2*)(hs + bl * 260);
            const ulonglong2* wv2 = (const ulonglong2*)(w1hs + jl * 260);
            ull a0 = 0, a1 = 0;
#pragma unroll 8
            for (int k4 = 0; k4 < 64; k4++) {
                ulonglong2 h2 = hv2[k4], w2v = wv2[k4];
                fma2(a0, h2.x, w2v.x);
                fma2(a1, h2.y, w2v.y);
            }
            add2(a0, a1);
            float2 f = unpack2(a0);
            float acc = f.x + f.y + oproj_reg;
            hst[bl * 17 + jl] = fmaxf(acc, 0.f);
            __syncthreads();
            const int o = tid & 63, bq = tid >> 6;
#pragma unroll
            for (int bb = 0; bb < 4; bb++) {
                int b_l = bq * 4 + bb;
                float pacc = 0.f;
#pragma unroll
                for (int k = 0; k < 16; k++)
                    pacc = fmaf(hst[b_l * 17 + k], w2s[(jt * 16 + k) * 64 + o], pacc);
                g_part[((size_t)(bt * 16 + b_l) * 16 + jt) * 64 + o] = pacc;
            }
            __syncthreads();
            barv += 16; bar_arrive(cnt);
            {
                float2 ev = *(const float2*)(eps + ((size_t)t * B_SZ + bt * 16) * 32 + tid * 2);
                *(float2*)(ebuf + tid * 2) = ev;
                abuf[tid] = act_seq[((size_t)(bt * 16 + (tid >> 4)) * T_STEPS + t) * 16 + (tid & 15)];
            }
            bar_wait(cnt, barv);
        }
    }

    {
        const int b = c;
        if (tid < 64) {
            float acc = b2s[tid];
#pragma unroll
            for (int q = 0; q < 16; q++)
                acc += ldcg1(g_part + ((size_t)b * 16 + q) * 64 + tid);
            o64s[tid] = acc;
        }
        __syncthreads();
        if (tid < 32) {
            int s = tid;
            float pm = o64s[s];
            float ps = softplusf_(o64s[32 + s]) + 0.1f;
            float e  = eps[((size_t)(T_STEPS - 1) * B_SZ + b) * 32 + s];
            float z  = fmaf(ps, e, pm);
            size_t base = ((size_t)b * T_STEPS + (T_STEPS - 1)) * OUT_D;
            out[base + 352 + s] = pm;
            out[base + 384 + s] = ps;
            out[base + 256 + s] = z;
        }
    }
}

// ---------------- GEMV (N=1): K=256 ----------------
__global__ void gemv_kernel(const float* __restrict__ A, int lda,
                            const float* __restrict__ w,
                            const float* __restrict__ bias, float* __restrict__ C, int act)
{
    const int warp = threadIdx.x >> 5, lane = threadIdx.x & 31;
    const int row = blockIdx.x * 8 + warp;
    const float* a = A + (size_t)row * lda;
    float acc = 0.f;
#pragma unroll
    for (int i = 0; i < 8; i++) acc = fmaf(a[lane + 32 * i], w[lane + 32 * i], acc);
#pragma unroll
    for (int off = 16; off; off >>= 1) acc += __shfl_xor_sync(0xffffffffu, acc, off);
    if (lane == 0) {
        float v = acc + bias[0];
        if (act == 3) v = sigmoidf_(v);
        C[(size_t)row * OUT_D] = v;
    }
}

// ---------------- driver ----------------
extern "C" void kernel_launch(void* const* d_in, const int* in_sizes, int n_in,
                              void* d_out, int out_size)
{
    const float* obs      = (const float*)d_in[0];
    const float* act      = (const float*)d_in[1];
    const float* eps      = (const float*)d_in[2];
    const float* prior_W1 = (const float*)d_in[3];
    const float* prior_b1 = (const float*)d_in[4];
    const float* prior_W2 = (const float*)d_in[5];
    const float* prior_b2 = (const float*)d_in[6];
    const float* post_W1  = (const float*)d_in[7];
    const float* post_b1  = (const float*)d_in[8];
    const float* post_W2  = (const float*)d_in[9];
    const float* post_b2  = (const float*)d_in[10];
    const float* W_ih     = (const float*)d_in[11];
    const float* b_ih     = (const float*)d_in[12];
    const float* W_hh     = (const float*)d_in[13];
    const float* b_hh     = (const float*)d_in[14];
    const float* dobs_W1  = (const float*)d_in[15];
    const float* dobs_b1  = (const float*)d_in[16];
    const float* dobs_W2  = (const float*)d_in[17];
    const float* dobs_b2  = (const float*)d_in[18];
    const float* drew_W1  = (const float*)d_in[19];
    const float* drew_b1  = (const float*)d_in[20];
    const float* drew_W2  = (const float*)d_in[21];
    const float* drew_b2  = (const float*)d_in[22];
    const float* dcont_W1 = (const float*)d_in[23];
    const float* dcont_b1 = (const float*)d_in[24];
    const float* dcont_W2 = (const float*)d_in[25];
    const float* dcont_b2 = (const float*)d_in[26];
    float* out = (float*)d_out;

    float *oproj_p = nullptr, *hid3_p = nullptr, *bcat_p = nullptr;
    cudaGetSymbolAddress((void**)&oproj_p, g_oproj);
    cudaGetSymbolAddress((void**)&hid3_p, g_hid3);
    cudaGetSymbolAddress((void**)&bcat_p, g_bcat);
    __nv_bfloat16 *wo_h, *wo_l, *wc_h, *wc_l, *wd_h, *wd_l, *wp_h, *wp_l;
    cudaGetSymbolAddress((void**)&wo_h, g_Wo_hi);
    cudaGetSymbolAddress((void**)&wo_l, g_Wo_lo);
    cudaGetSymbolAddress((void**)&wc_h, g_Wc_hi);
    cudaGetSymbolAddress((void**)&wc_l, g_Wc_lo);
    cudaGetSymbolAddress((void**)&wd_h, g_Wd_hi);
    cudaGetSymbolAddress((void**)&wd_l, g_Wd_lo);
    cudaGetSymbolAddress((void**)&wp_h, g_Wp_hi);
    cudaGetSymbolAddress((void**)&wp_l, g_Wp_lo);

    static int attrs_set = 0;
    if (!attrs_set) {
        cudaFuncSetAttribute(scan_kernel, cudaFuncAttributeMaxDynamicSharedMemorySize, SMEM_BYTES);
        attrs_set = 1;
    }

    prep_kernel<<<1680, 256>>>(W_ih, W_hh);
    prep2_kernel<<<4, 256>>>(prior_b1, dobs_b1, drew_b1, dcont_b1);
    prep3_kernel<<<3392, 256>>>(post_W1, prior_W1, dobs_W1, drew_W1, dcont_W1,
                                dobs_W2, prior_W2);

    // Phase A: o_proj = obs @ W1o + post_b1  (tensor, split-bf16)
    mmagemm_kernel<<<dim3(4, BT / 128), 256>>>(
        1024, 1024, obs, 1024, wo_h, wo_l, 256, post_b1, oproj_p, 256, 0);

    // Phase B: persistent sequential scan (unchanged, fp32)
    scan_kernel<<<NCTA, 256, SMEM_BYTES>>>(out, act, eps, b_ih, b_hh,
                                           post_W1, post_W2, post_b2);

    // Phase C: merged decoder/prior L1 (K=288 padded to 320)
    mmagemm_kernel<<<dim3(16, BT / 128), 256>>>(
        320, 288, out, OUT_D, wc_h, wc_l, 1024, bcat_p, hid3_p, 1024, 1);
    // prior L2 (mean/std)
    mmagemm_kernel<<<dim3(1, BT / 128), 256>>>(
        256, 256, hid3_p, 1024, wp_h, wp_l, 64, prior_b2, out + 288, OUT_D, 2);
    // obs decoder L2
    mmagemm_kernel<<<dim3(16, BT / 128), 256>>>(
        256, 256, hid3_p + 256, 1024, wd_h, wd_l, 1024, dobs_b2, out + 416, OUT_D, 0);
    // reward / continuation heads
    gemv_kernel<<<BT / 8, 256>>>(hid3_p + 512, 1024, drew_W2, drew_b2, out + 1440, 0);
    gemv_kernel<<<BT / 8, 256>>>(hid3_p + 768, 1024, dcont_W2, dcont_b2, out + 1441, 3);
}

// round 14
// speedup vs baseline: 1.2790x; 1.0285x over previous
#include <cuda_runtime.h>
#include <cuda_bf16.h>
#include <cstdint>
#include <math.h>

#define T_STEPS 512
#define B_SZ    128
#define BT      (B_SZ * T_STEPS)
#define OUT_D   1442
#define NCTA    128

typedef unsigned long long ull;

// ---------------- scratch (static device globals; no allocation) ----------------
__device__ __align__(16) float g_oproj[BT * 256];          // obs @ W1o + post_b1, [B][T][256]
__device__ __align__(16) float g_hid3 [(size_t)BT * 1024]; // decoder hidden (fp32 kept for cols>=512)
__device__ __align__(16) float g_WihT [768 * 304];         // W_ih transposed: [n][k]
__device__ __align__(16) float g_WhhT [768 * 256];         // W_hh transposed: [n][k]
__device__ __align__(16) float g_bcat [1024];
__device__ __align__(16) float g_part [B_SZ * 16 * 64];    // partial o64: [b][jt][64]
__device__ __align__(16) float g_state[B_SZ * 256];        // h only
__device__ unsigned g_cnts[8 * 32];                        // per-group barrier counters

// bf16-split weights in [k][n] layout (hi + lo)
__device__ __align__(16) __nv_bfloat16 g_Wo_hi[1024 * 256], g_Wo_lo[1024 * 256];   // oproj  (K=1024,N=256)
__device__ __align__(16) __nv_bfloat16 g_Wc_hi[320 * 1024], g_Wc_lo[320 * 1024];   // Wcat   (K=320, N=1024)
__device__ __align__(16) __nv_bfloat16 g_Wd_hi[256 * 1024], g_Wd_lo[256 * 1024];   // dobsW2 (K=256, N=1024)
__device__ __align__(16) __nv_bfloat16 g_Wp_hi[256 * 64],   g_Wp_lo[256 * 64];     // priorW2(K=256, N=64)

// pre-split A matrices (bf16 hi/lo), row-major [row][k]
__device__ __align__(16) __nv_bfloat16 g_Ao_hi[(size_t)BT * 1024], g_Ao_lo[(size_t)BT * 1024]; // obs
__device__ __align__(16) __nv_bfloat16 g_Az_hi[(size_t)BT * 320],  g_Az_lo[(size_t)BT * 320];  // [h|z] pad320
__device__ __align__(16) __nv_bfloat16 g_Ah_hi[(size_t)BT * 512],  g_Ah_lo[(size_t)BT * 512];  // hid3 cols 0..511

__device__ __forceinline__ float sigmoidf_(float x) { return 1.f / (1.f + expf(-x)); }
__device__ __forceinline__ float softplusf_(float x) {
    return fmaxf(x, 0.f) + log1pf(expf(-fabsf(x)));
}

// bf16 split packers
__device__ __forceinline__ uint32_t pack_hi2(float a, float b) {
    __nv_bfloat16 ha = __float2bfloat16(a), hb = __float2bfloat16(b);
    return (uint32_t)__bfloat16_as_ushort(ha) | ((uint32_t)__bfloat16_as_ushort(hb) << 16);
}
__device__ __forceinline__ uint32_t pack_lo2(float a, float b) {
    __nv_bfloat16 ha = __float2bfloat16(a), hb = __float2bfloat16(b);
    float la = a - __bfloat162float(ha), lb = b - __bfloat162float(hb);
    return (uint32_t)__bfloat16_as_ushort(__float2bfloat16(la))
         | ((uint32_t)__bfloat16_as_ushort(__float2bfloat16(lb)) << 16);
}

// packed fp32x2 helpers
__device__ __forceinline__ void fma2(ull& d, ull a, ull b) {
    asm("fma.rn.f32x2 %0, %1, %2, %0;" : "+l"(d) : "l"(a), "l"(b));
}
__device__ __forceinline__ void add2(ull& d, ull a) {
    asm("add.rn.f32x2 %0, %0, %1;" : "+l"(d) : "l"(a));
}
__device__ __forceinline__ float2 unpack2(ull v) {
    float2 f; asm("mov.b64 {%0, %1}, %2;" : "=f"(f.x), "=f"(f.y) : "l"(v)); return f;
}

// L2-direct loads
__device__ __forceinline__ float4 ldcg4(const float* p) {
    float4 v;
    asm volatile("ld.global.cg.v4.f32 {%0,%1,%2,%3}, [%4];"
                 : "=f"(v.x), "=f"(v.y), "=f"(v.z), "=f"(v.w) : "l"(p));
    return v;
}
__device__ __forceinline__ float ldcg1(const float* p) {
    float v;
    asm volatile("ld.global.cg.f32 %0, [%1];" : "=f"(v) : "l"(p));
    return v;
}

// scoped-atomic barrier primitives (no MEMBAR.GL)
__device__ __forceinline__ void bar_arrive(unsigned* cnt) {
    if (threadIdx.x == 0)
        asm volatile("red.release.gpu.global.add.u32 [%0], %1;" :: "l"(cnt), "r"(1u) : "memory");
}
__device__ __forceinline__ void bar_wait(unsigned* cnt, unsigned target) {
    if (threadIdx.x == 0) {
        unsigned v;
        do {
            asm volatile("ld.acquire.gpu.global.u32 %0, [%1];" : "=r"(v) : "l"(cnt) : "memory");
        } while (v < target);
    }
    __syncthreads();
}

// ---------------- mma.sync helpers ----------------
__device__ __forceinline__ uint32_t smem_u32(const void* p) {
    uint32_t a;
    asm("{ .reg .u64 t; cvta.to.shared.u64 t, %1; cvt.u32.u64 %0, t; }" : "=r"(a) : "l"(p));
    return a;
}
__device__ __forceinline__ void ldsm4(uint32_t* r, uint32_t addr) {
    asm volatile("ldmatrix.sync.aligned.m8n8.x4.shared.b16 {%0,%1,%2,%3}, [%4];"
                 : "=r"(r[0]), "=r"(r[1]), "=r"(r[2]), "=r"(r[3]) : "r"(addr));
}
__device__ __forceinline__ void ldsm4t(uint32_t* r, uint32_t addr) {
    asm volatile("ldmatrix.sync.aligned.m8n8.x4.trans.shared.b16 {%0,%1,%2,%3}, [%4];"
                 : "=r"(r[0]), "=r"(r[1]), "=r"(r[2]), "=r"(r[3]) : "r"(addr));
}
__device__ __forceinline__ void mma16816(float* c, const uint32_t* a, uint32_t b0, uint32_t b1) {
    asm volatile("mma.sync.aligned.m16n8k16.row.col.f32.bf16.bf16.f32 "
                 "{%0,%1,%2,%3}, {%4,%5,%6,%7}, {%8,%9}, {%0,%1,%2,%3};"
                 : "+f"(c[0]), "+f"(c[1]), "+f"(c[2]), "+f"(c[3])
                 : "r"(a[0]), "r"(a[1]), "r"(a[2]), "r"(a[3]), "r"(b0), "r"(b1));
}

// ---------------- prep: transpose GRU weights, reset barriers ----------------
__global__ void prep_kernel(const float* __restrict__ W_ih, const float* __restrict__ W_hh) {
    if (blockIdx.x == 0 && threadIdx.x < 8) g_cnts[threadIdx.x * 32] = 0u;
    int idx = blockIdx.x * 256 + threadIdx.x;
    const int n1 = 768 * 304;
    if (idx < n1) {
        int n = idx / 304, k = idx - n * 304;
        g_WihT[idx] = W_ih[k * 768 + n];
    } else {
        int r = idx - n1;
        int n = r >> 8, k = r & 255;
        g_WhhT[r] = W_hh[k * 768 + n];
    }
}

// bias concat for Wcat
__global__ void prep2_kernel(const float* __restrict__ prior_b1, const float* __restrict__ dobs_b1,
                             const float* __restrict__ drew_b1,  const float* __restrict__ dcont_b1)
{
    int j = blockIdx.x * 256 + threadIdx.x;        // 1024
    int g = j >> 8, jj = j & 255;
    float b;
    if (g == 0)      b = prior_b1[jj];
    else if (g == 1) b = dobs_b1[jj];
    else if (g == 2) b = drew_b1[jj];
    else             b = dcont_b1[jj];
    g_bcat[j] = b;
}

// build bf16-split weights, [k][n] layout
__global__ void prep3_kernel(const float* __restrict__ post_W1,
                             const float* __restrict__ prior_W1, const float* __restrict__ dobs_W1,
                             const float* __restrict__ drew_W1,  const float* __restrict__ dcont_W1,
                             const float* __restrict__ dobs_W2,  const float* __restrict__ prior_W2)
{
    const int No = 1024 * 256, Nc = 320 * 1024, Nd = 256 * 1024;
    int idx = blockIdx.x * 256 + threadIdx.x;
    float w; __nv_bfloat16* hi; __nv_bfloat16* lo; int off;
    if (idx < No) {
        int k = idx >> 8, n = idx & 255;
        w = post_W1[(size_t)(256 + k) * 256 + n];
        hi = g_Wo_hi; lo = g_Wo_lo; off = idx;
    } else if (idx < No + Nc) {
        int r = idx - No;
        int k = r >> 10, n = r & 1023;
        int g = n >> 8, j = n & 255;
        if (k >= 288) w = 0.f;
        else if (g == 0) w = (k < 256) ? prior_W1[k * 256 + j] : 0.f;
        else if (g == 1) w = dobs_W1[(size_t)k * 256 + j];
        else if (g == 2) w = drew_W1[(size_t)k * 256 + j];
        else             w = dcont_W1[(size_t)k * 256 + j];
        hi = g_Wc_hi; lo = g_Wc_lo; off = r;
    } else if (idx < No + Nc + Nd) {
        int r = idx - No - Nc;
        w = dobs_W2[r];                       // already [k][n]
        hi = g_Wd_hi; lo = g_Wd_lo; off = r;
    } else {
        int r = idx - No - Nc - Nd;
        w = prior_W2[r];                      // already [k][n]
        hi = g_Wp_hi; lo = g_Wp_lo; off = r;
    }
    __nv_bfloat16 h = __float2bfloat16(w);
    hi[off] = h;
    lo[off] = __float2bfloat16(w - __bfloat162float(h));
}

// convert obs -> g_Ao (hi/lo), 4 elements per thread
__global__ void cvt_obs_kernel(const float* __restrict__ obs) {
    size_t i = ((size_t)blockIdx.x * 256 + threadIdx.x) * 4;
    float4 v = *(const float4*)(obs + i);
    *(uint2*)(g_Ao_hi + i) = make_uint2(pack_hi2(v.x, v.y), pack_hi2(v.z, v.w));
    *(uint2*)(g_Ao_lo + i) = make_uint2(pack_lo2(v.x, v.y), pack_lo2(v.z, v.w));
}

// convert out rows [h|z] (288) -> g_Az [BT][320] (zero-padded)
__global__ void cvt_out_kernel(const float* __restrict__ out) {
    size_t i = (size_t)blockIdx.x * 256 + threadIdx.x;   // BT*80
    int row = (int)(i / 80), k = (int)(i % 80) * 4;
    float x0 = 0.f, x1 = 0.f, x2 = 0.f, x3 = 0.f;
    if (k < 288) {
        const float* p = out + (size_t)row * OUT_D + k;
        float2 a = *(const float2*)p;
        float2 b = *(const float2*)(p + 2);
        x0 = a.x; x1 = a.y; x2 = b.x; x3 = b.y;
    }
    size_t o = (size_t)row * 320 + k;
    *(uint2*)(g_Az_hi + o) = make_uint2(pack_hi2(x0, x1), pack_hi2(x2, x3));
    *(uint2*)(g_Az_lo + o) = make_uint2(pack_lo2(x0, x1), pack_lo2(x2, x3));
}

// ---------------- split-bf16 tensor GEMM, pre-split A (tile 128x64, K chunks of 32) ----------------
#define AP 40   // A smem row stride (bf16)
#define BP 72   // B smem row stride (bf16)

__global__ void __launch_bounds__(256) mmagemm_kernel(
    int K, const __nv_bfloat16* __restrict__ Ahi_g, const __nv_bfloat16* __restrict__ Alo_g, int ldA,
    const __nv_bfloat16* __restrict__ Whi, const __nv_bfloat16* __restrict__ Wlo, int ldw,
    const float* __restrict__ bias, float* __restrict__ C, int ldc, int act,
    __nv_bfloat16* __restrict__ Chi, __nv_bfloat16* __restrict__ Clo, int bfN)
{
    __shared__ __align__(16) __nv_bfloat16 Ahi[128 * AP], Alo[128 * AP];
    __shared__ __align__(16) __nv_bfloat16 Bhi[32 * BP],  Blo[32 * BP];

    const int tid = threadIdx.x, lane = tid & 31, wid = tid >> 5;
    const int warp_m = wid & 3, warp_n = wid >> 2;       // 4 x 2 warp grid
    const int rowBase = blockIdx.y * 128, colBase = blockIdx.x * 64;

    float acc[2][4][4];
#pragma unroll
    for (int mt = 0; mt < 2; mt++)
#pragma unroll
        for (int nt = 0; nt < 4; nt++)
#pragma unroll
            for (int i = 0; i < 4; i++) acc[mt][nt][i] = 0.f;

    const uint32_t aHiB = smem_u32(Ahi), aLoB = smem_u32(Alo);
    const uint32_t bHiB = smem_u32(Bhi), bLoB = smem_u32(Blo);

    for (int kk = 0; kk < K; kk += 32) {
        // ---- stage A: pure bf16 copies (pre-split) ----
        {
            const int r = tid >> 1, kh = (tid & 1) * 16;
            size_t src = (size_t)(rowBase + r) * ldA + kk + kh;
            *(uint4*)(Ahi + r * AP + kh)     = *(const uint4*)(Ahi_g + src);
            *(uint4*)(Ahi + r * AP + kh + 8) = *(const uint4*)(Ahi_g + src + 8);
            *(uint4*)(Alo + r * AP + kh)     = *(const uint4*)(Alo_g + src);
            *(uint4*)(Alo + r * AP + kh + 8) = *(const uint4*)(Alo_g + src + 8);
        }
        // ---- stage B: 32 k-rows x 64 n ----
        {
            const int bk = tid >> 3, bn = (tid & 7) * 8;
            size_t src = (size_t)(kk + bk) * ldw + colBase + bn;
            *(uint4*)(Bhi + bk * BP + bn) = *(const uint4*)(Whi + src);
            *(uint4*)(Blo + bk * BP + bn) = *(const uint4*)(Wlo + src);
        }
        __syncthreads();

        // ---- compute: 2 k16 steps ----
#pragma unroll
        for (int k16 = 0; k16 < 32; k16 += 16) {
            uint32_t ah[2][4], al[2][4], bh[2][4], bl[2][4];
#pragma unroll
            for (int mt = 0; mt < 2; mt++) {
                uint32_t off = ((warp_m * 32 + mt * 16 + (lane & 15)) * AP
                                + k16 + ((lane >> 4) << 3)) * 2;
                ldsm4(ah[mt], aHiB + off);
                ldsm4(al[mt], aLoB + off);
            }
#pragma unroll
            for (int np = 0; np < 2; np++) {
                uint32_t off = ((k16 + (lane & 15)) * BP
                                + warp_n * 32 + np * 16 + ((lane >> 4) << 3)) * 2;
                ldsm4t(bh[np], bHiB + off);
                ldsm4t(bl[np], bLoB + off);
            }
#pragma unroll
            for (int mt = 0; mt < 2; mt++)
#pragma unroll
                for (int nt = 0; nt < 4; nt++) {
                    int np = nt >> 1, bi = (nt & 1) * 2;
                    mma16816(acc[mt][nt], ah[mt], bh[np][bi], bh[np][bi + 1]);
                    mma16816(acc[mt][nt], ah[mt], bl[np][bi], bl[np][bi + 1]);
                    mma16816(acc[mt][nt], al[mt], bh[np][bi], bh[np][bi + 1]);
                }
        }
        __syncthreads();
    }

    // ---- epilogue ----
    const bool bfpath = (Chi != nullptr) && (colBase < bfN);
#pragma unroll
    for (int mt = 0; mt < 2; mt++) {
#pragma unroll
        for (int nt = 0; nt < 4; nt++) {
            int row0 = rowBase + warp_m * 32 + mt * 16 + (lane >> 2);
            int col  = colBase + warp_n * 32 + (nt >> 1) * 16 + (nt & 1) * 8 + (lane & 3) * 2;
            float v0 = acc[mt][nt][0], v1 = acc[mt][nt][1];
            float v2 = acc[mt][nt][2], v3 = acc[mt][nt][3];
            if (bias) {
                float b0 = bias[col], b1 = bias[col + 1];
                v0 += b0; v1 += b1; v2 += b0; v3 += b1;
            }
            if (act == 1) {
                v0 = fmaxf(v0, 0.f); v1 = fmaxf(v1, 0.f);
                v2 = fmaxf(v2, 0.f); v3 = fmaxf(v3, 0.f);
            } else if (act == 2) {
                if (col >= 32)     { v0 = softplusf_(v0) + 0.1f; v2 = softplusf_(v2) + 0.1f; }
                if (col + 1 >= 32) { v1 = softplusf_(v1) + 0.1f; v3 = softplusf_(v3) + 0.1f; }
            }
            if (bfpath) {
                size_t o0 = (size_t)row0 * bfN + col;
                size_t o1 = (size_t)(row0 + 8) * bfN + col;
                *(uint32_t*)(Chi + o0) = pack_hi2(v0, v1);
                *(uint32_t*)(Clo + o0) = pack_lo2(v0, v1);
                *(uint32_t*)(Chi + o1) = pack_hi2(v2, v3);
                *(uint32_t*)(Clo + o1) = pack_lo2(v2, v3);
            } else {
                *(float2*)(C + (size_t)row0 * ldc + col)       = make_float2(v0, v1);
                *(float2*)(C + (size_t)(row0 + 8) * ldc + col) = make_float2(v2, v3);
            }
        }
    }
}

// ---------------- persistent scan kernel (exact R6 structure — best known) ----------------
#define SM_WGRU 0
#define SM_W1H  26880
#define SM_W2   (SM_W1H + 16*260)
#define SM_B2   (SM_W2 + 16384)
#define SM_XS   (SM_B2 + 64)
#define SM_HST  (SM_XS + 16*308)
#define SM_O64  (SM_HST + 16*17)
#define SM_STG  (SM_O64 + 1024)
#define SM_EBUF (SM_STG + 16*96)
#define SM_ABUF (SM_EBUF + 512)
#define SM_FLOATS (SM_ABUF + 256)
#define SMEM_BYTES (SM_FLOATS * 4)

__global__ void __launch_bounds__(256, 1) scan_kernel(
    float* __restrict__ out, const float* __restrict__ act_seq,
    const float* __restrict__ eps,
    const float* __restrict__ b_ih, const float* __restrict__ b_hh,
    const float* __restrict__ post_W1, const float* __restrict__ post_W2,
    const float* __restrict__ post_b2)
{
    extern __shared__ float sm[];
    float* wgru = sm + SM_WGRU;
    float* w1hs = sm + SM_W1H;
    float* w2s  = sm + SM_W2;
    float* b2s  = sm + SM_B2;
    float* xs   = sm + SM_XS;
    float* hst  = sm + SM_HST;
    float* o64s = sm + SM_O64;
    float* stg  = sm + SM_STG;
    float* ebuf = sm + SM_EBUF;
    float* abuf = sm + SM_ABUF;

    const int tid = threadIdx.x;
    const int c   = blockIdx.x;
    const int jt  = c & 15;
    const int bt  = c >> 4;
    const int jl  = tid >> 4;
    const int bl  = tid & 15;
    const int jc  = jt * 16 + jl;
    const int b_a = bt * 16 + bl;
    unsigned* cnt = &g_cnts[bt * 32];

    for (int idx = tid; idx < 16 * 1680; idx += 256) {
        int j_ = idx / 1680, r = idx - j_ * 1680;
        int j = jt * 16 + j_;
        float v;
        if (r < 912) { int g = r / 304, k = r - g * 304; v = g_WihT[(size_t)(g * 256 + j) * 304 + k]; }
        else { int r2 = r - 912; int g = r2 >> 8, k = r2 & 255; v = g_WhhT[(size_t)(g * 256 + j) * 256 + k]; }
        wgru[idx] = v;
    }
    for (int idx = tid; idx < 16 * 256; idx += 256) {
        int j_ = idx >> 8, k = idx & 255;
        w1hs[j_ * 260 + k] = post_W1[(size_t)k * 256 + jt * 16 + j_];
    }
    for (int idx = tid; idx < 16384; idx += 256) w2s[idx] = post_W2[idx];
    if (tid < 64) b2s[tid] = post_b2[tid];
    __syncthreads();

    const float bir = b_ih[jc], biz = b_ih[jc + 256], bin_ = b_ih[jc + 512];
    const float bhr = b_hh[jc], bhz = b_hh[jc + 256], bhn = b_hh[jc + 512];

    unsigned barv = 0;

    for (int t = 0; t < T_STEPS; t++) {
        float oproj_reg = g_oproj[((size_t)b_a * T_STEPS + t) * 256 + jc];

        if (t == 0) {
            int b_l = tid >> 4, j_l = tid & 15;
            g_state[(bt * 16 + b_l) * 256 + jt * 16 + j_l] = 0.f;
            __syncthreads();
            barv += 16; bar_arrive(cnt);
            out[((size_t)(bt * 16 + b_l) * T_STEPS + 0) * OUT_D + jt * 16 + j_l] = 0.f;
            bar_wait(cnt, barv);
        } else {
            int b_l = tid >> 4, og = (tid & 15) * 4;
            float4 racc = *(const float4*)(b2s + og);
#pragma unroll
            for (int q = 0; q < 16; q++) {
                float4 v = ldcg4(g_part + ((size_t)(bt * 16 + b_l) * 16 + q) * 64 + og);
                racc.x += v.x; racc.y += v.y; racc.z += v.z; racc.w += v.w;
            }
            float4 hv[4];
#pragma unroll
            for (int p = 0; p < 4; p++) {
                int idx = tid + p * 256;
                int bl_ = idx >> 6, k4 = idx & 63;
                hv[p] = ldcg4(g_state + (bt * 16 + bl_) * 256 + k4 * 4);
            }
            *(float4*)(o64s + b_l * 64 + og) = racc;
#pragma unroll
            for (int p = 0; p < 4; p++) {
                int idx = tid + p * 256;
                int bl_ = idx >> 6, k4 = idx & 63;
                *(float4*)(xs + bl_ * 308 + k4 * 4) = hv[p];
            }
            xs[(tid >> 4) * 308 + 288 + (tid & 15)] = abuf[tid];
            __syncthreads();
            for (int idx = tid; idx < 512; idx += 256) {
                int bl_ = idx >> 5, s = idx & 31;
                float pm = o64s[bl_ * 64 + s];
                float ps = softplusf_(o64s[bl_ * 64 + 32 + s]) + 0.1f;
                float e  = ebuf[bl_ * 32 + s];
                float z  = fmaf(ps, e, pm);
                xs[bl_ * 308 + 256 + s] = z;
                if (jt == 0) {
                    stg[bl_ * 96 + s]      = pm;
                    stg[bl_ * 96 + 32 + s] = ps;
                    stg[bl_ * 96 + 64 + s] = z;
                }
            }
            __syncthreads();

            const ulonglong2* xv  = (const ulonglong2*)(xs + bl * 308);
            const ulonglong2* wir = (const ulonglong2*)(wgru + jl * 1680);
            const ulonglong2* wiz = (const ulonglong2*)(wgru + jl * 1680 + 304);
            const ulonglong2* win = (const ulonglong2*)(wgru + jl * 1680 + 608);
            const ulonglong2* whr = (const ulonglong2*)(wgru + jl * 1680 + 912);
            const ulonglong2* whz = (const ulonglong2*)(wgru + jl * 1680 + 1168);
            const ulonglong2* whn = (const ulonglong2*)(wgru + jl * 1680 + 1424);

            ull air0=0, air1=0, aiz0=0, aiz1=0, ain0=0, ain1=0;
            ull ahr0=0, ahr1=0, ahz0=0, ahz1=0, ahn0=0, ahn1=0;
#pragma unroll 4
            for (int k4 = 0; k4 < 64; k4++) {
                ulonglong2 x2 = xv[k4];
                ulonglong2 w;
                w = wir[k4]; fma2(air0, x2.x, w.x); fma2(air1, x2.y, w.y);
                w = wiz[k4]; fma2(aiz0, x2.x, w.x); fma2(aiz1, x2.y, w.y);
                w = win[k4]; fma2(ain0, x2.x, w.x); fma2(ain1, x2.y, w.y);
                w = whr[k4]; fma2(ahr0, x2.x, w.x); fma2(ahr1, x2.y, w.y);
                w = whz[k4]; fma2(ahz0, x2.x, w.x); fma2(ahz1, x2.y, w.y);
                w = whn[k4]; fma2(ahn0, x2.x, w.x); fma2(ahn1, x2.y, w.y);
            }
#pragma unroll
            for (int k4 = 64; k4 < 76; k4++) {
                ulonglong2 x2 = xv[k4];
                ulonglong2 w;
                w = wir[k4]; fma2(air0, x2.x, w.x); fma2(air1, x2.y, w.y);
                w = wiz[k4]; fma2(aiz0, x2.x, w.x); fma2(aiz1, x2.y, w.y);
                w = win[k4]; fma2(ain0, x2.x, w.x); fma2(ain1, x2.y, w.y);
            }
            add2(air0, air1); add2(aiz0, aiz1); add2(ain0, ain1);
            add2(ahr0, ahr1); add2(ahz0, ahz1); add2(ahn0, ahn1);
            float2 fr = unpack2(air0), fz = unpack2(aiz0), fn = unpack2(ain0);
            float2 gr = unpack2(ahr0), gz = unpack2(ahz0), gn = unpack2(ahn0);
            float sir = fr.x + fr.y + bir;
            float siz = fz.x + fz.y + biz;
            float sin_= fn.x + fn.y + bin_;
            float shr = gr.x + gr.y + bhr;
            float shz = gz.x + gz.y + bhz;
            float shn = gn.x + gn.y + bhn;

            float r  = sigmoidf_(sir + shr);
            float zg = sigmoidf_(siz + shz);
            float n  = tanhf(sin_ + r * shn);
            float hprev = xs[bl * 308 + jc];
            float hnew  = (1.f - zg) * n + zg * hprev;
            hst[bl * 17 + jl] = hnew;
            __syncthreads();
            {
                int b_l2 = tid >> 4, j_l = tid & 15;
                g_state[(bt * 16 + b_l2) * 256 + jt * 16 + j_l] = hst[b_l2 * 17 + j_l];
            }
            __syncthreads();
            barv += 16; bar_arrive(cnt);
            {
                int b_l2 = tid >> 4, j_l = tid & 15;
                out[((size_t)(bt * 16 + b_l2) * T_STEPS + t) * OUT_D + jt * 16 + j_l] =
                    hst[b_l2 * 17 + j_l];
            }
            if (jt == 0) {
                for (int idx = tid; idx < 512; idx += 256) {
                    int bl_ = idx >> 5, s = idx & 31;
                    size_t base = ((size_t)(bt * 16 + bl_) * T_STEPS + (t - 1)) * OUT_D;
                    out[base + 352 + s] = stg[bl_ * 96 + s];
                    out[base + 384 + s] = stg[bl_ * 96 + 32 + s];
                    out[base + 256 + s] = stg[bl_ * 96 + 64 + s];
                }
            }
            bar_wait(cnt, barv);
        }

        {
            float* hs = xs;
#pragma unroll
            for (int p = 0; p < 4; p++) {
                int idx = tid + p * 256;
                int b_l = idx >> 6, k4 = idx & 63;
                float4 v = ldcg4(g_state + (bt * 16 + b_l) * 256 + k4 * 4);
                *(float4*)(hs + b_l * 260 + k4 * 4) = v;
            }
            __syncthreads();
            const ulonglong2* hv2 = (const ulonglong2*)(hs + bl * 260);
            const ulonglong2* wv2 = (const ulonglong2*)(w1hs + jl * 260);
            ull a0 = 0, a1 = 0;
#pragma unroll 8
            for (int k4 = 0; k4 < 64; k4++) {
                ulonglong2 h2 = hv2[k4], w2v = wv2[k4];
                fma2(a0, h2.x, w2v.x);
                fma2(a1, h2.y, w2v.y);
            }
            add2(a0, a1);
            float2 f = unpack2(a0);
            float acc = f.x + f.y + oproj_reg;
            hst[bl * 17 + jl] = fmaxf(acc, 0.f);
            __syncthreads();
            const int o = tid & 63, bq = tid >> 6;
#pragma unroll
            for (int bb = 0; bb < 4; bb++) {
                int b_l = bq * 4 + bb;
                float pacc = 0.f;
#pragma unroll
                for (int k = 0; k < 16; k++)
                    pacc = fmaf(hst[b_l * 17 + k], w2s[(jt * 16 + k) * 64 + o], pacc);
                g_part[((size_t)(bt * 16 + b_l) * 16 + jt) * 64 + o] = pacc;
            }
            __syncthreads();
            barv += 16; bar_arrive(cnt);
            {
                float2 ev = *(const float2*)(eps + ((size_t)t * B_SZ + bt * 16) * 32 + tid * 2);
                *(float2*)(ebuf + tid * 2) = ev;
                abuf[tid] = act_seq[((size_t)(bt * 16 + (tid >> 4)) * T_STEPS + t) * 16 + (tid & 15)];
            }
            bar_wait(cnt, barv);
        }
    }

    {
        const int b = c;
        if (tid < 64) {
            float acc = b2s[tid];
#pragma unroll
            for (int q = 0; q < 16; q++)
                acc += ldcg1(g_part + ((size_t)b * 16 + q) * 64 + tid);
            o64s[tid] = acc;
        }
        __syncthreads();
        if (tid < 32) {
            int s = tid;
            float pm = o64s[s];
            float ps = softplusf_(o64s[32 + s]) + 0.1f;
            float e  = eps[((size_t)(T_STEPS - 1) * B_SZ + b) * 32 + s];
            float z  = fmaf(ps, e, pm);
            size_t base = ((size_t)b * T_STEPS + (T_STEPS - 1)) * OUT_D;
            out[base + 352 + s] = pm;
            out[base + 384 + s] = ps;
            out[base + 256 + s] = z;
        }
    }
}

// ---------------- GEMV (N=1): K=256 ----------------
__global__ void gemv_kernel(const float* __restrict__ A, int lda,
                            const float* __restrict__ w,
                            const float* __restrict__ bias, float* __restrict__ C, int act)
{
    const int warp = threadIdx.x >> 5, lane = threadIdx.x & 31;
    const int row = blockIdx.x * 8 + warp;
    const float* a = A + (size_t)row * lda;
    float acc = 0.f;
#pragma unroll
    for (int i = 0; i < 8; i++) acc = fmaf(a[lane + 32 * i], w[lane + 32 * i], acc);
#pragma unroll
    for (int off = 16; off; off >>= 1) acc += __shfl_xor_sync(0xffffffffu, acc, off);
    if (lane == 0) {
        float v = acc + bias[0];
        if (act == 3) v = sigmoidf_(v);
        C[(size_t)row * OUT_D] = v;
    }
}

// ---------------- driver ----------------
extern "C" void kernel_launch(void* const* d_in, const int* in_sizes, int n_in,
                              void* d_out, int out_size)
{
    const float* obs      = (const float*)d_in[0];
    const float* act      = (const float*)d_in[1];
    const float* eps      = (const float*)d_in[2];
    const float* prior_W1 = (const float*)d_in[3];
    const float* prior_b1 = (const float*)d_in[4];
    const float* prior_W2 = (const float*)d_in[5];
    const float* prior_b2 = (const float*)d_in[6];
    const float* post_W1  = (const float*)d_in[7];
    const float* post_b1  = (const float*)d_in[8];
    const float* post_W2  = (const float*)d_in[9];
    const float* post_b2  = (const float*)d_in[10];
    const float* W_ih     = (const float*)d_in[11];
    const float* b_ih     = (const float*)d_in[12];
    const float* W_hh     = (const float*)d_in[13];
    const float* b_hh     = (const float*)d_in[14];
    const float* dobs_W1  = (const float*)d_in[15];
    const float* dobs_b1  = (const float*)d_in[16];
    const float* dobs_W2  = (const float*)d_in[17];
    const float* dobs_b2  = (const float*)d_in[18];
    const float* drew_W1  = (const float*)d_in[19];
    const float* drew_b1  = (const float*)d_in[20];
    const float* drew_W2  = (const float*)d_in[21];
    const float* drew_b2  = (const float*)d_in[22];
    const float* dcont_W1 = (const float*)d_in[23];
    const float* dcont_b1 = (const float*)d_in[24];
    const float* dcont_W2 = (const float*)d_in[25];
    const float* dcont_b2 = (const float*)d_in[26];
    float* out = (float*)d_out;

    float *oproj_p = nullptr, *hid3_p = nullptr, *bcat_p = nullptr;
    cudaGetSymbolAddress((void**)&oproj_p, g_oproj);
    cudaGetSymbolAddress((void**)&hid3_p, g_hid3);
    cudaGetSymbolAddress((void**)&bcat_p, g_bcat);
    __nv_bfloat16 *wo_h, *wo_l, *wc_h, *wc_l, *wd_h, *wd_l, *wp_h, *wp_l;
    __nv_bfloat16 *ao_h, *ao_l, *az_h, *az_l, *ah_h, *ah_l;
    cudaGetSymbolAddress((void**)&wo_h, g_Wo_hi);
    cudaGetSymbolAddress((void**)&wo_l, g_Wo_lo);
    cudaGetSymbolAddress((void**)&wc_h, g_Wc_hi);
    cudaGetSymbolAddress((void**)&wc_l, g_Wc_lo);
    cudaGetSymbolAddress((void**)&wd_h, g_Wd_hi);
    cudaGetSymbolAddress((void**)&wd_l, g_Wd_lo);
    cudaGetSymbolAddress((void**)&wp_h, g_Wp_hi);
    cudaGetSymbolAddress((void**)&wp_l, g_Wp_lo);
    cudaGetSymbolAddress((void**)&ao_h, g_Ao_hi);
    cudaGetSymbolAddress((void**)&ao_l, g_Ao_lo);
    cudaGetSymbolAddress((void**)&az_h, g_Az_hi);
    cudaGetSymbolAddress((void**)&az_l, g_Az_lo);
    cudaGetSymbolAddress((void**)&ah_h, g_Ah_hi);
    cudaGetSymbolAddress((void**)&ah_l, g_Ah_lo);

    static int attrs_set = 0;
    if (!attrs_set) {
        cudaFuncSetAttribute(scan_kernel, cudaFuncAttributeMaxDynamicSharedMemorySize, SMEM_BYTES);
        attrs_set = 1;
    }

    prep_kernel<<<1680, 256>>>(W_ih, W_hh);
    prep2_kernel<<<4, 256>>>(prior_b1, dobs_b1, drew_b1, dcont_b1);
    prep3_kernel<<<3392, 256>>>(post_W1, prior_W1, dobs_W1, drew_W1, dcont_W1,
                                dobs_W2, prior_W2);
    cvt_obs_kernel<<<BT * 1024 / 4 / 256, 256>>>(obs);

    // Phase A: o_proj = obs @ W1o + post_b1  (tensor, split-bf16, pre-split A)
    mmagemm_kernel<<<dim3(4, BT / 128), 256>>>(
        1024, ao_h, ao_l, 1024, wo_h, wo_l, 256, post_b1, oproj_p, 256, 0,
        nullptr, nullptr, 0);

    // Phase B: persistent sequential scan (unchanged, fp32)
    scan_kernel<<<NCTA, 256, SMEM_BYTES>>>(out, act, eps, b_ih, b_hh,
                                           post_W1, post_W2, post_b2);

    // convert [h|z] rows of out -> g_Az (pre-split, padded to K=320)
    cvt_out_kernel<<<BT * 80 / 256, 256>>>(out);

    // Phase C: merged decoder/prior L1 — cols<512 dual-written as bf16 (g_Ah)
    mmagemm_kernel<<<dim3(16, BT / 128), 256>>>(
        320, az_h, az_l, 320, wc_h, wc_l, 1024, bcat_p, hid3_p, 1024, 1,
        ah_h, ah_l, 512);
    // prior L2 (mean/std): A = g_Ah cols 0..255
    mmagemm_kernel<<<dim3(1, BT / 128), 256>>>(
        256, ah_h, ah_l, 512, wp_h, wp_l, 64, prior_b2, out + 288, OUT_D, 2,
        nullptr, nullptr, 0);
    // obs decoder L2: A = g_Ah cols 256..511
    mmagemm_kernel<<<dim3(16, BT / 128), 256>>>(
        256, ah_h + 256, ah_l + 256, 512, wd_h, wd_l, 1024, dobs_b2, out + 416, OUT_D, 0,
        nullptr, nullptr, 0);
    // reward / continuation heads (fp32 hid3 cols 512..1023)
    gemv_kernel<<<BT / 8, 256>>>(hid3_p + 512, 1024, drew_W2, drew_b2, out + 1440, 0);
    gemv_kernel<<<BT / 8, 256>>>(hid3_p + 768, 1024, dcont_W2, dcont_b2, out + 1441, 3);
}

// round 15
// speedup vs baseline: 1.5304x; 1.1966x over previous
#include <cuda_runtime.h>
#include <cuda_bf16.h>
#include <cstdint>
#include <math.h>

#define T_STEPS 512
#define B_SZ    128
#define BT      (B_SZ * T_STEPS)
#define OUT_D   1442
#define NCTA    128

typedef unsigned long long ull;

// ---------------- scratch (static device globals; no allocation) ----------------
__device__ __align__(16) float g_oproj[BT * 256];
__device__ __align__(16) float g_hid3 [(size_t)BT * 1024];
__device__ __align__(16) float g_bcat [1024];
__device__ __align__(16) float g_part [B_SZ * 16 * 64];
__device__ __align__(16) float g_state[B_SZ * 256];
__device__ unsigned g_cnts[8 * 32];

// GRU weights bf16-split, [k][n] layout (n = gate*256 + hcol)
__device__ __align__(16) __nv_bfloat16 g_Wih_hi[304 * 768], g_Wih_lo[304 * 768];
__device__ __align__(16) __nv_bfloat16 g_Whh_hi[256 * 768], g_Whh_lo[256 * 768];

// bf16-split weights in [k][n] layout (hi + lo)
__device__ __align__(16) __nv_bfloat16 g_Wo_hi[1024 * 256], g_Wo_lo[1024 * 256];
__device__ __align__(16) __nv_bfloat16 g_Wc_hi[320 * 1024], g_Wc_lo[320 * 1024];
__device__ __align__(16) __nv_bfloat16 g_Wd_hi[256 * 1024], g_Wd_lo[256 * 1024];
__device__ __align__(16) __nv_bfloat16 g_Wp_hi[256 * 64],   g_Wp_lo[256 * 64];

// pre-split A matrices (bf16 hi/lo), row-major [row][k]
__device__ __align__(16) __nv_bfloat16 g_Ao_hi[(size_t)BT * 1024], g_Ao_lo[(size_t)BT * 1024];
__device__ __align__(16) __nv_bfloat16 g_Az_hi[(size_t)BT * 320],  g_Az_lo[(size_t)BT * 320];
__device__ __align__(16) __nv_bfloat16 g_Ah_hi[(size_t)BT * 512],  g_Ah_lo[(size_t)BT * 512];

__device__ __forceinline__ float sigmoidf_(float x) { return 1.f / (1.f + expf(-x)); }
__device__ __forceinline__ float softplusf_(float x) {
    return fmaxf(x, 0.f) + log1pf(expf(-fabsf(x)));
}

// bf16 split packers
__device__ __forceinline__ uint32_t pack_hi2(float a, float b) {
    __nv_bfloat16 ha = __float2bfloat16(a), hb = __float2bfloat16(b);
    return (uint32_t)__bfloat16_as_ushort(ha) | ((uint32_t)__bfloat16_as_ushort(hb) << 16);
}
__device__ __forceinline__ uint32_t pack_lo2(float a, float b) {
    __nv_bfloat16 ha = __float2bfloat16(a), hb = __float2bfloat16(b);
    float la = a - __bfloat162float(ha), lb = b - __bfloat162float(hb);
    return (uint32_t)__bfloat16_as_ushort(__float2bfloat16(la))
         | ((uint32_t)__bfloat16_as_ushort(__float2bfloat16(lb)) << 16);
}

// packed fp32x2 helpers
__device__ __forceinline__ void fma2(ull& d, ull a, ull b) {
    asm("fma.rn.f32x2 %0, %1, %2, %0;" : "+l"(d) : "l"(a), "l"(b));
}
__device__ __forceinline__ void add2(ull& d, ull a) {
    asm("add.rn.f32x2 %0, %0, %1;" : "+l"(d) : "l"(a));
}
__device__ __forceinline__ float2 unpack2(ull v) {
    float2 f; asm("mov.b64 {%0, %1}, %2;" : "=f"(f.x), "=f"(f.y) : "l"(v)); return f;
}

// L2-direct loads
__device__ __forceinline__ float4 ldcg4(const float* p) {
    float4 v;
    asm volatile("ld.global.cg.v4.f32 {%0,%1,%2,%3}, [%4];"
                 : "=f"(v.x), "=f"(v.y), "=f"(v.z), "=f"(v.w) : "l"(p));
    return v;
}
__device__ __forceinline__ float ldcg1(const float* p) {
    float v;
    asm volatile("ld.global.cg.f32 %0, [%1];" : "=f"(v) : "l"(p));
    return v;
}

// scoped-atomic barrier primitives
__device__ __forceinline__ void bar_arrive(unsigned* cnt) {
    if (threadIdx.x == 0)
        asm volatile("red.release.gpu.global.add.u32 [%0], %1;" :: "l"(cnt), "r"(1u) : "memory");
}
__device__ __forceinline__ void bar_wait(unsigned* cnt, unsigned target) {
    if (threadIdx.x == 0) {
        unsigned v;
        do {
            asm volatile("ld.acquire.gpu.global.u32 %0, [%1];" : "=r"(v) : "l"(cnt) : "memory");
        } while (v < target);
    }
    __syncthreads();
}

// ---------------- mma.sync helpers ----------------
__device__ __forceinline__ uint32_t smem_u32(const void* p) {
    uint32_t a;
    asm("{ .reg .u64 t; cvta.to.shared.u64 t, %1; cvt.u32.u64 %0, t; }" : "=r"(a) : "l"(p));
    return a;
}
__device__ __forceinline__ void ldsm4(uint32_t* r, uint32_t addr) {
    asm volatile("ldmatrix.sync.aligned.m8n8.x4.shared.b16 {%0,%1,%2,%3}, [%4];"
                 : "=r"(r[0]), "=r"(r[1]), "=r"(r[2]), "=r"(r[3]) : "r"(addr));
}
__device__ __forceinline__ void ldsm4t(uint32_t* r, uint32_t addr) {
    asm volatile("ldmatrix.sync.aligned.m8n8.x4.trans.shared.b16 {%0,%1,%2,%3}, [%4];"
                 : "=r"(r[0]), "=r"(r[1]), "=r"(r[2]), "=r"(r[3]) : "r"(addr));
}
__device__ __forceinline__ void mma16816(float* c, const uint32_t* a, uint32_t b0, uint32_t b1) {
    asm volatile("mma.sync.aligned.m16n8k16.row.col.f32.bf16.bf16.f32 "
                 "{%0,%1,%2,%3}, {%4,%5,%6,%7}, {%8,%9}, {%0,%1,%2,%3};"
                 : "+f"(c[0]), "+f"(c[1]), "+f"(c[2]), "+f"(c[3])
                 : "r"(a[0]), "r"(a[1]), "r"(a[2]), "r"(a[3]), "r"(b0), "r"(b1));
}

// ---------------- prep: split GRU weights bf16 hi/lo ([k][n], no transpose) ----------------
__global__ void prep_kernel(const float* __restrict__ W_ih, const float* __restrict__ W_hh) {
    if (blockIdx.x == 0 && threadIdx.x < 8) g_cnts[threadIdx.x * 32] = 0u;
    int idx = blockIdx.x * 256 + threadIdx.x;
    const int n1 = 304 * 768;
    float w; __nv_bfloat16 *hi, *lo; int off;
    if (idx < n1) { w = W_ih[idx]; hi = g_Wih_hi; lo = g_Wih_lo; off = idx; }
    else { off = idx - n1; w = W_hh[off]; hi = g_Whh_hi; lo = g_Whh_lo; }
    __nv_bfloat16 h = __float2bfloat16(w);
    hi[off] = h;
    lo[off] = __float2bfloat16(w - __bfloat162float(h));
}

// bias concat for Wcat
__global__ void prep2_kernel(const float* __restrict__ prior_b1, const float* __restrict__ dobs_b1,
                             const float* __restrict__ drew_b1,  const float* __restrict__ dcont_b1)
{
    int j = blockIdx.x * 256 + threadIdx.x;
    int g = j >> 8, jj = j & 255;
    float b;
    if (g == 0)      b = prior_b1[jj];
    else if (g == 1) b = dobs_b1[jj];
    else if (g == 2) b = drew_b1[jj];
    else             b = dcont_b1[jj];
    g_bcat[j] = b;
}

// build bf16-split weights, [k][n] layout
__global__ void prep3_kernel(const float* __restrict__ post_W1,
                             const float* __restrict__ prior_W1, const float* __restrict__ dobs_W1,
                             const float* __restrict__ drew_W1,  const float* __restrict__ dcont_W1,
                             const float* __restrict__ dobs_W2,  const float* __restrict__ prior_W2)
{
    const int No = 1024 * 256, Nc = 320 * 1024, Nd = 256 * 1024;
    int idx = blockIdx.x * 256 + threadIdx.x;
    float w; __nv_bfloat16* hi; __nv_bfloat16* lo; int off;
    if (idx < No) {
        int k = idx >> 8, n = idx & 255;
        w = post_W1[(size_t)(256 + k) * 256 + n];
        hi = g_Wo_hi; lo = g_Wo_lo; off = idx;
    } else if (idx < No + Nc) {
        int r = idx - No;
        int k = r >> 10, n = r & 1023;
        int g = n >> 8, j = n & 255;
        if (k >= 288) w = 0.f;
        else if (g == 0) w = (k < 256) ? prior_W1[k * 256 + j] : 0.f;
        else if (g == 1) w = dobs_W1[(size_t)k * 256 + j];
        else if (g == 2) w = drew_W1[(size_t)k * 256 + j];
        else             w = dcont_W1[(size_t)k * 256 + j];
        hi = g_Wc_hi; lo = g_Wc_lo; off = r;
    } else if (idx < No + Nc + Nd) {
        int r = idx - No - Nc;
        w = dobs_W2[r];
        hi = g_Wd_hi; lo = g_Wd_lo; off = r;
    } else {
        int r = idx - No - Nc - Nd;
        w = prior_W2[r];
        hi = g_Wp_hi; lo = g_Wp_lo; off = r;
    }
    __nv_bfloat16 h = __float2bfloat16(w);
    hi[off] = h;
    lo[off] = __float2bfloat16(w - __bfloat162float(h));
}

// convert obs -> g_Ao (hi/lo)
__global__ void cvt_obs_kernel(const float* __restrict__ obs) {
    size_t i = ((size_t)blockIdx.x * 256 + threadIdx.x) * 4;
    float4 v = *(const float4*)(obs + i);
    *(uint2*)(g_Ao_hi + i) = make_uint2(pack_hi2(v.x, v.y), pack_hi2(v.z, v.w));
    *(uint2*)(g_Ao_lo + i) = make_uint2(pack_lo2(v.x, v.y), pack_lo2(v.z, v.w));
}

// convert out rows [h|z] (288) -> g_Az [BT][320] (zero-padded)
__global__ void cvt_out_kernel(const float* __restrict__ out) {
    size_t i = (size_t)blockIdx.x * 256 + threadIdx.x;   // BT*80
    int row = (int)(i / 80), k = (int)(i % 80) * 4;
    float x0 = 0.f, x1 = 0.f, x2 = 0.f, x3 = 0.f;
    if (k < 288) {
        const float* p = out + (size_t)row * OUT_D + k;
        float2 a = *(const float2*)p;
        float2 b = *(const float2*)(p + 2);
        x0 = a.x; x1 = a.y; x2 = b.x; x3 = b.y;
    }
    size_t o = (size_t)row * 320 + k;
    *(uint2*)(g_Az_hi + o) = make_uint2(pack_hi2(x0, x1), pack_hi2(x2, x3));
    *(uint2*)(g_Az_lo + o) = make_uint2(pack_lo2(x0, x1), pack_lo2(x2, x3));
}

// ---------------- split-bf16 tensor GEMM, pre-split A (tile 128x64, K chunks of 32) ----------------
#define AP 40
#define BP 72

__global__ void __launch_bounds__(256) mmagemm_kernel(
    int K, const __nv_bfloat16* __restrict__ Ahi_g, const __nv_bfloat16* __restrict__ Alo_g, int ldA,
    const __nv_bfloat16* __restrict__ Whi, const __nv_bfloat16* __restrict__ Wlo, int ldw,
    const float* __restrict__ bias, float* __restrict__ C, int ldc, int act,
    __nv_bfloat16* __restrict__ Chi, __nv_bfloat16* __restrict__ Clo, int bfN)
{
    __shared__ __align__(16) __nv_bfloat16 Ahi[128 * AP], Alo[128 * AP];
    __shared__ __align__(16) __nv_bfloat16 Bhi[32 * BP],  Blo[32 * BP];

    const int tid = threadIdx.x, lane = tid & 31, wid = tid >> 5;
    const int warp_m = wid & 3, warp_n = wid >> 2;
    const int rowBase = blockIdx.y * 128, colBase = blockIdx.x * 64;

    float acc[2][4][4];
#pragma unroll
    for (int mt = 0; mt < 2; mt++)
#pragma unroll
        for (int nt = 0; nt < 4; nt++)
#pragma unroll
            for (int i = 0; i < 4; i++) acc[mt][nt][i] = 0.f;

    const uint32_t aHiB = smem_u32(Ahi), aLoB = smem_u32(Alo);
    const uint32_t bHiB = smem_u32(Bhi), bLoB = smem_u32(Blo);

    for (int kk = 0; kk < K; kk += 32) {
        {
            const int r = tid >> 1, kh = (tid & 1) * 16;
            size_t src = (size_t)(rowBase + r) * ldA + kk + kh;
            *(uint4*)(Ahi + r * AP + kh)     = *(const uint4*)(Ahi_g + src);
            *(uint4*)(Ahi + r * AP + kh + 8) = *(const uint4*)(Ahi_g + src + 8);
            *(uint4*)(Alo + r * AP + kh)     = *(const uint4*)(Alo_g + src);
            *(uint4*)(Alo + r * AP + kh + 8) = *(const uint4*)(Alo_g + src + 8);
        }
        {
            const int bk = tid >> 3, bn = (tid & 7) * 8;
            size_t src = (size_t)(kk + bk) * ldw + colBase + bn;
            *(uint4*)(Bhi + bk * BP + bn) = *(const uint4*)(Whi + src);
            *(uint4*)(Blo + bk * BP + bn) = *(const uint4*)(Wlo + src);
        }
        __syncthreads();

#pragma unroll
        for (int k16 = 0; k16 < 32; k16 += 16) {
            uint32_t ah[2][4], al[2][4], bh[2][4], bl[2][4];
#pragma unroll
            for (int mt = 0; mt < 2; mt++) {
                uint32_t off = ((warp_m * 32 + mt * 16 + (lane & 15)) * AP
                                + k16 + ((lane >> 4) << 3)) * 2;
                ldsm4(ah[mt], aHiB + off);
                ldsm4(al[mt], aLoB + off);
            }
#pragma unroll
            for (int np = 0; np < 2; np++) {
                uint32_t off = ((k16 + (lane & 15)) * BP
                                + warp_n * 32 + np * 16 + ((lane >> 4) << 3)) * 2;
                ldsm4t(bh[np], bHiB + off);
                ldsm4t(bl[np], bLoB + off);
            }
#pragma unroll
            for (int mt = 0; mt < 2; mt++)
#pragma unroll
                for (int nt = 0; nt < 4; nt++) {
                    int np = nt >> 1, bi = (nt & 1) * 2;
                    mma16816(acc[mt][nt], ah[mt], bh[np][bi], bh[np][bi + 1]);
                    mma16816(acc[mt][nt], ah[mt], bl[np][bi], bl[np][bi + 1]);
                    mma16816(acc[mt][nt], al[mt], bh[np][bi], bh[np][bi + 1]);
                }
        }
        __syncthreads();
    }

    const bool bfpath = (Chi != nullptr) && (colBase < bfN);
#pragma unroll
    for (int mt = 0; mt < 2; mt++) {
#pragma unroll
        for (int nt = 0; nt < 4; nt++) {
            int row0 = rowBase + warp_m * 32 + mt * 16 + (lane >> 2);
            int col  = colBase + warp_n * 32 + (nt >> 1) * 16 + (nt & 1) * 8 + (lane & 3) * 2;
            float v0 = acc[mt][nt][0], v1 = acc[mt][nt][1];
            float v2 = acc[mt][nt][2], v3 = acc[mt][nt][3];
            if (bias) {
                float b0 = bias[col], b1 = bias[col + 1];
                v0 += b0; v1 += b1; v2 += b0; v3 += b1;
            }
            if (act == 1) {
                v0 = fmaxf(v0, 0.f); v1 = fmaxf(v1, 0.f);
                v2 = fmaxf(v2, 0.f); v3 = fmaxf(v3, 0.f);
            } else if (act == 2) {
                if (col >= 32)     { v0 = softplusf_(v0) + 0.1f; v2 = softplusf_(v2) + 0.1f; }
                if (col + 1 >= 32) { v1 = softplusf_(v1) + 0.1f; v3 = softplusf_(v3) + 0.1f; }
            }
            if (bfpath) {
                size_t o0 = (size_t)row0 * bfN + col;
                size_t o1 = (size_t)(row0 + 8) * bfN + col;
                *(uint32_t*)(Chi + o0) = pack_hi2(v0, v1);
                *(uint32_t*)(Clo + o0) = pack_lo2(v0, v1);
                *(uint32_t*)(Chi + o1) = pack_hi2(v2, v3);
                *(uint32_t*)(Clo + o1) = pack_lo2(v2, v3);
            } else {
                *(float2*)(C + (size_t)row0 * ldc + col)       = make_float2(v0, v1);
                *(float2*)(C + (size_t)(row0 + 8) * ldc + col) = make_float2(v2, v3);
            }
        }
    }
}

// ---------------- persistent scan kernel: tensor-core GRU ----------------
// smem byte offsets
#define SB_WIH_HI 0
#define SB_WIH_LO 29184
#define SB_WHH_HI 58368
#define SB_WHH_LO 82944
#define SB_W1H    107520
#define SB_W2     124160
#define SB_B2     189696
#define SB_XS     189952          // fp32 xs[16][308] (BC) / xbf hi+lo union (phase A)
#define SB_XBH    189952          // bf16 [16][304]
#define SB_XBL    199680          // bf16 [16][304]
#define SB_HST    209664
#define SB_O64    210752
#define SB_STG    214848
#define SB_EBUF   220992
#define SB_ABUF   223040
#define SB_GBUF   224064          // fp32 [2][16][52]
#define SMEM_BYTES 230720

__global__ void __launch_bounds__(256, 1) scan_kernel(
    float* __restrict__ out, const float* __restrict__ act_seq,
    const float* __restrict__ eps,
    const float* __restrict__ b_ih, const float* __restrict__ b_hh,
    const float* __restrict__ post_W1, const float* __restrict__ post_W2,
    const float* __restrict__ post_b2)
{
    extern __shared__ char smb[];
    __nv_bfloat16* wih_h = (__nv_bfloat16*)(smb + SB_WIH_HI);
    __nv_bfloat16* wih_l = (__nv_bfloat16*)(smb + SB_WIH_LO);
    __nv_bfloat16* whh_h = (__nv_bfloat16*)(smb + SB_WHH_HI);
    __nv_bfloat16* whh_l = (__nv_bfloat16*)(smb + SB_WHH_LO);
    float* w1hs = (float*)(smb + SB_W1H);   // [jl][k] stride 260
    float* w2s  = (float*)(smb + SB_W2);
    float* b2s  = (float*)(smb + SB_B2);
    float* xs   = (float*)(smb + SB_XS);    // BC: [16][260] fp32 h buffer
    __nv_bfloat16* xbh = (__nv_bfloat16*)(smb + SB_XBH);
    __nv_bfloat16* xbl = (__nv_bfloat16*)(smb + SB_XBL);
    float* hst  = (float*)(smb + SB_HST);   // [16][17]
    float* o64s = (float*)(smb + SB_O64);
    float* stg  = (float*)(smb + SB_STG);
    float* ebuf = (float*)(smb + SB_EBUF);
    float* abuf = (float*)(smb + SB_ABUF);
    float* gbuf = (float*)(smb + SB_GBUF);  // [2][16][52]

    const int tid = threadIdx.x;
    const int lane = tid & 31, wid = tid >> 5;
    const int c   = blockIdx.x;
    const int jt  = c & 15;
    const int bt  = c >> 4;
    const int jl  = tid >> 4;     // BC mapping
    const int bl  = tid & 15;
    const int jc  = jt * 16 + jl;
    const int b_a = bt * 16 + bl;
    unsigned* cnt = &g_cnts[bt * 32];

    // ---- preload weights into SMEM (once) ----
    for (int idx = tid; idx < 304 * 48; idx += 256) {
        int k = idx / 48, n = idx - k * 48;
        int col = (n >> 4) * 256 + jt * 16 + (n & 15);
        wih_h[idx] = g_Wih_hi[k * 768 + col];
        wih_l[idx] = g_Wih_lo[k * 768 + col];
    }
    for (int idx = tid; idx < 256 * 48; idx += 256) {
        int k = idx / 48, n = idx - k * 48;
        int col = (n >> 4) * 256 + jt * 16 + (n & 15);
        whh_h[idx] = g_Whh_hi[k * 768 + col];
        whh_l[idx] = g_Whh_lo[k * 768 + col];
    }
    for (int idx = tid; idx < 16 * 256; idx += 256) {
        int j_ = idx >> 8, k = idx & 255;
        w1hs[j_ * 260 + k] = post_W1[(size_t)k * 256 + jt * 16 + j_];
    }
    for (int idx = tid; idx < 16384; idx += 256) w2s[idx] = post_W2[idx];
    if (tid < 64) b2s[tid] = post_b2[tid];
    __syncthreads();

    // gate-combine mapping (row = tid>>4, col = tid&15) biases
    const int gcol = jt * 16 + (tid & 15);
    const float bir = b_ih[gcol], biz = b_ih[gcol + 256], bin_ = b_ih[gcol + 512];
    const float bhr = b_hh[gcol], bhz = b_hh[gcol + 256], bhn = b_hh[gcol + 512];

    const uint32_t xbhB = smem_u32(xbh), xblB = smem_u32(xbl);
    const uint32_t wihhB = smem_u32(wih_h), wihlB = smem_u32(wih_l);
    const uint32_t whhhB = smem_u32(whh_h), whhlB = smem_u32(whh_l);

    unsigned barv = 0;

    for (int t = 0; t < T_STEPS; t++) {
        float oproj_reg = g_oproj[((size_t)b_a * T_STEPS + t) * 256 + jc];

        // ========== Phase A ==========
        if (t == 0) {
            int b_l = tid >> 4, j_l = tid & 15;
            g_state[(bt * 16 + b_l) * 256 + jt * 16 + j_l] = 0.f;
            __syncthreads();
            barv += 16; bar_arrive(cnt);
            out[((size_t)(bt * 16 + b_l) * T_STEPS + 0) * OUT_D + jt * 16 + j_l] = 0.f;
            bar_wait(cnt, barv);
        } else {
            float hprev_reg = ldcg1(g_state + (bt * 16 + (tid >> 4)) * 256 + gcol);
            // --- (a) o64 reduce + h loads -> bf16 xbf ---
            int b_l = tid >> 4, og = (tid & 15) * 4;
            float4 racc = *(const float4*)(b2s + og);
#pragma unroll
            for (int q = 0; q < 16; q++) {
                float4 v = ldcg4(g_part + ((size_t)(bt * 16 + b_l) * 16 + q) * 64 + og);
                racc.x += v.x; racc.y += v.y; racc.z += v.z; racc.w += v.w;
            }
            float4 hv[4];
#pragma unroll
            for (int p = 0; p < 4; p++) {
                int idx = tid + p * 256;
                int bl_ = idx >> 6, k4 = idx & 63;
                hv[p] = ldcg4(g_state + (bt * 16 + bl_) * 256 + k4 * 4);
            }
            *(float4*)(o64s + b_l * 64 + og) = racc;
#pragma unroll
            for (int p = 0; p < 4; p++) {
                int idx = tid + p * 256;
                int bl_ = idx >> 6, k4 = idx & 63;
                *(uint2*)(xbh + bl_ * 304 + k4 * 4) =
                    make_uint2(pack_hi2(hv[p].x, hv[p].y), pack_hi2(hv[p].z, hv[p].w));
                *(uint2*)(xbl + bl_ * 304 + k4 * 4) =
                    make_uint2(pack_lo2(hv[p].x, hv[p].y), pack_lo2(hv[p].z, hv[p].w));
            }
            {   // action -> xbf cols 288..303
                int bl2 = tid >> 4, ka = tid & 15;
                float av = abuf[tid];
                __nv_bfloat16 ah = __float2bfloat16(av);
                xbh[bl2 * 304 + 288 + ka] = ah;
                xbl[bl2 * 304 + 288 + ka] = __float2bfloat16(av - __bfloat162float(ah));
            }
            __syncthreads();
            // --- (b) sample z_{t-1}, z -> xbf cols 256..287, stage outputs ---
            for (int idx = tid; idx < 512; idx += 256) {
                int bl_ = idx >> 5, s = idx & 31;
                float pm = o64s[bl_ * 64 + s];
                float ps = softplusf_(o64s[bl_ * 64 + 32 + s]) + 0.1f;
                float e  = ebuf[bl_ * 32 + s];
                float z  = fmaf(ps, e, pm);
                __nv_bfloat16 zh = __float2bfloat16(z);
                xbh[bl_ * 304 + 256 + s] = zh;
                xbl[bl_ * 304 + 256 + s] = __float2bfloat16(z - __bfloat162float(zh));
                if (jt == 0) {
                    stg[bl_ * 96 + s]      = pm;
                    stg[bl_ * 96 + 32 + s] = ps;
                    stg[bl_ * 96 + 64 + s] = z;
                }
            }
            __syncthreads();

            // --- (c) tensor-core GRU: jobs (part, n16) for warps 0..5 ---
            if (wid < 6) {
                const int part = wid / 3;        // 0 = ih (K=304), 1 = hh (K=256)
                const int n16  = wid % 3;
                const uint32_t bHiB = part ? whhhB : wihhB;
                const uint32_t bLoB = part ? whhlB : wihlB;
                const int nk16 = part ? 16 : 19;
                float c0[4] = {0, 0, 0, 0}, c1[4] = {0, 0, 0, 0};
#pragma unroll 1
                for (int k16i = 0; k16i < nk16; k16i++) {
                    int k16 = k16i * 16;
                    uint32_t ah[4], al[4], bh[4], blo[4];
                    uint32_t aoff = ((lane & 15) * 304 + k16 + ((lane >> 4) << 3)) * 2;
                    ldsm4(ah, xbhB + aoff);
                    ldsm4(al, xblB + aoff);
                    uint32_t boff = ((k16 + (lane & 15)) * 48 + n16 * 16 + ((lane >> 4) << 3)) * 2;
                    ldsm4t(bh, bHiB + boff);
                    ldsm4t(blo, bLoB + boff);
                    mma16816(c0, ah, bh[0], bh[1]);
                    mma16816(c0, ah, blo[0], blo[1]);
                    mma16816(c0, al, bh[0], bh[1]);
                    mma16816(c1, ah, bh[2], bh[3]);
                    mma16816(c1, ah, blo[2], blo[3]);
                    mma16816(c1, al, bh[2], bh[3]);
                }
                float* gb = gbuf + part * 832;   // 16*52
                int r0 = lane >> 2, cc = n16 * 16 + (lane & 3) * 2;
                gb[r0 * 52 + cc]           = c0[0];
                gb[r0 * 52 + cc + 1]       = c0[1];
                gb[(r0 + 8) * 52 + cc]     = c0[2];
                gb[(r0 + 8) * 52 + cc + 1] = c0[3];
                gb[r0 * 52 + cc + 8]           = c1[0];
                gb[r0 * 52 + cc + 9]           = c1[1];
                gb[(r0 + 8) * 52 + cc + 8]     = c1[2];
                gb[(r0 + 8) * 52 + cc + 9]     = c1[3];
            }
            __syncthreads();

            // --- (d) gate combine (row = tid>>4, col = tid&15) ---
            {
                int row = tid >> 4, col = tid & 15;
                const float* g0 = gbuf + row * 52;
                const float* g1 = gbuf + 832 + row * 52;
                float sir = g0[col]      + bir;
                float siz = g0[16 + col] + biz;
                float sin_= g0[32 + col] + bin_;
                float shr = g1[col]      + bhr;
                float shz = g1[16 + col] + bhz;
                float shn = g1[32 + col] + bhn;
                float r  = sigmoidf_(sir + shr);
                float zg = sigmoidf_(siz + shz);
                float n  = tanhf(sin_ + r * shn);
                hst[row * 17 + col] = (1.f - zg) * n + zg * hprev_reg;
            }
            __syncthreads();
            // --- (e) g_state write ---
            {
                int b_l2 = tid >> 4, j_l = tid & 15;
                g_state[(bt * 16 + b_l2) * 256 + jt * 16 + j_l] = hst[b_l2 * 17 + j_l];
            }
            __syncthreads();
            barv += 16; bar_arrive(cnt);
            // --- (f) deferred out writes ---
            {
                int b_l2 = tid >> 4, j_l = tid & 15;
                out[((size_t)(bt * 16 + b_l2) * T_STEPS + t) * OUT_D + jt * 16 + j_l] =
                    hst[b_l2 * 17 + j_l];
            }
            if (jt == 0) {
                for (int idx = tid; idx < 512; idx += 256) {
                    int bl_ = idx >> 5, s = idx & 31;
                    size_t base = ((size_t)(bt * 16 + bl_) * T_STEPS + (t - 1)) * OUT_D;
                    out[base + 352 + s] = stg[bl_ * 96 + s];
                    out[base + 384 + s] = stg[bl_ * 96 + 32 + s];
                    out[base + 256 + s] = stg[bl_ * 96 + 64 + s];
                }
            }
            bar_wait(cnt, barv);
        }

        // ========== Phase BC: hid slice + partial o64 (SIMT f32x2, unchanged) ==========
        {
            float* hs = xs;   // [16][260]
#pragma unroll
            for (int p = 0; p < 4; p++) {
                int idx = tid + p * 256;
                int b_l = idx >> 6, k4 = idx & 63;
                float4 v = ldcg4(g_state + (bt * 16 + b_l) * 256 + k4 * 4);
                *(float4*)(hs + b_l * 260 + k4 * 4) = v;
            }
            __syncthreads();
            const ulonglong2* hv2 = (const ulonglong2*)(hs + bl * 260);
            const ulonglong2* wv2 = (const ulonglong2*)(w1hs + jl * 260);
            ull a0 = 0, a1 = 0;
#pragma unroll 8
            for (int k4 = 0; k4 < 64; k4++) {
                ulonglong2 h2 = hv2[k4], w2v = wv2[k4];
                fma2(a0, h2.x, w2v.x);
                fma2(a1, h2.y, w2v.y);
            }
            add2(a0, a1);
            float2 f = unpack2(a0);
            float acc = f.x + f.y + oproj_reg;
            hst[bl * 17 + jl] = fmaxf(acc, 0.f);
            __syncthreads();
            const int o = tid & 63, bq = tid >> 6;
#pragma unroll
            for (int bb = 0; bb < 4; bb++) {
                int b_l = bq * 4 + bb;
                float pacc = 0.f;
#pragma unroll
                for (int k = 0; k < 16; k++)
                    pacc = fmaf(hst[b_l * 17 + k], w2s[(jt * 16 + k) * 64 + o], pacc);
                g_part[((size_t)(bt * 16 + b_l) * 16 + jt) * 64 + o] = pacc;
            }
            __syncthreads();
            barv += 16; bar_arrive(cnt);
            {
                float2 ev = *(const float2*)(eps + ((size_t)t * B_SZ + bt * 16) * 32 + tid * 2);
                *(float2*)(ebuf + tid * 2) = ev;
                abuf[tid] = act_seq[((size_t)(bt * 16 + (tid >> 4)) * T_STEPS + t) * 16 + (tid & 15)];
            }
            bar_wait(cnt, barv);
        }
    }

    // ========== epilogue: reduce partials for t=511, write outputs ==========
    {
        const int b = c;
        if (tid < 64) {
            float acc = b2s[tid];
#pragma unroll
            for (int q = 0; q < 16; q++)
                acc += ldcg1(g_part + ((size_t)b * 16 + q) * 64 + tid);
            o64s[tid] = acc;
        }
        __syncthreads();
        if (tid < 32) {
            int s = tid;
            float pm = o64s[s];
            float ps = softplusf_(o64s[32 + s]) + 0.1f;
            float e  = eps[((size_t)(T_STEPS - 1) * B_SZ + b) * 32 + s];
            float z  = fmaf(ps, e, pm);
            size_t base = ((size_t)b * T_STEPS + (T_STEPS - 1)) * OUT_D;
            out[base + 352 + s] = pm;
            out[base + 384 + s] = ps;
            out[base + 256 + s] = z;
        }
    }
}

// ---------------- GEMV (N=1): K=256 ----------------
__global__ void gemv_kernel(const float* __restrict__ A, int lda,
                            const float* __restrict__ w,
                            const float* __restrict__ bias, float* __restrict__ C, int act)
{
    const int warp = threadIdx.x >> 5, lane = threadIdx.x & 31;
    const int row = blockIdx.x * 8 + warp;
    const float* a = A + (size_t)row * lda;
    float acc = 0.f;
#pragma unroll
    for (int i = 0; i < 8; i++) acc = fmaf(a[lane + 32 * i], w[lane + 32 * i], acc);
#pragma unroll
    for (int off = 16; off; off >>= 1) acc += __shfl_xor_sync(0xffffffffu, acc, off);
    if (lane == 0) {
        float v = acc + bias[0];
        if (act == 3) v = sigmoidf_(v);
        C[(size_t)row * OUT_D] = v;
    }
}

// ---------------- driver ----------------
extern "C" void kernel_launch(void* const* d_in, const int* in_sizes, int n_in,
                              void* d_out, int out_size)
{
    const float* obs      = (const float*)d_in[0];
    const float* act      = (const float*)d_in[1];
    const float* eps      = (const float*)d_in[2];
    const float* prior_W1 = (const float*)d_in[3];
    const float* prior_b1 = (const float*)d_in[4];
    const float* prior_W2 = (const float*)d_in[5];
    const float* prior_b2 = (const float*)d_in[6];
    const float* post_W1  = (const float*)d_in[7];
    const float* post_b1  = (const float*)d_in[8];
    const float* post_W2  = (const float*)d_in[9];
    const float* post_b2  = (const float*)d_in[10];
    const float* W_ih     = (const float*)d_in[11];
    const float* b_ih     = (const float*)d_in[12];
    const float* W_hh     = (const float*)d_in[13];
    const float* b_hh     = (const float*)d_in[14];
    const float* dobs_W1  = (const float*)d_in[15];
    const float* dobs_b1  = (const float*)d_in[16];
    const float* dobs_W2  = (const float*)d_in[17];
    const float* dobs_b2  = (const float*)d_in[18];
    const float* drew_W1  = (const float*)d_in[19];
    const float* drew_b1  = (const float*)d_in[20];
    const float* drew_W2  = (const float*)d_in[21];
    const float* drew_b2  = (const float*)d_in[22];
    const float* dcont_W1 = (const float*)d_in[23];
    const float* dcont_b1 = (const float*)d_in[24];
    const float* dcont_W2 = (const float*)d_in[25];
    const float* dcont_b2 = (const float*)d_in[26];
    float* out = (float*)d_out;

    float *oproj_p = nullptr, *hid3_p = nullptr, *bcat_p = nullptr;
    cudaGetSymbolAddress((void**)&oproj_p, g_oproj);
    cudaGetSymbolAddress((void**)&hid3_p, g_hid3);
    cudaGetSymbolAddress((void**)&bcat_p, g_bcat);
    __nv_bfloat16 *wo_h, *wo_l, *wc_h, *wc_l, *wd_h, *wd_l, *wp_h, *wp_l;
    __nv_bfloat16 *ao_h, *ao_l, *az_h, *az_l, *ah_h, *ah_l;
    cudaGetSymbolAddress((void**)&wo_h, g_Wo_hi);
    cudaGetSymbolAddress((void**)&wo_l, g_Wo_lo);
    cudaGetSymbolAddress((void**)&wc_h, g_Wc_hi);
    cudaGetSymbolAddress((void**)&wc_l, g_Wc_lo);
    cudaGetSymbolAddress((void**)&wd_h, g_Wd_hi);
    cudaGetSymbolAddress((void**)&wd_l, g_Wd_lo);
    cudaGetSymbolAddress((void**)&wp_h, g_Wp_hi);
    cudaGetSymbolAddress((void**)&wp_l, g_Wp_lo);
    cudaGetSymbolAddress((void**)&ao_h, g_Ao_hi);
    cudaGetSymbolAddress((void**)&ao_l, g_Ao_lo);
    cudaGetSymbolAddress((void**)&az_h, g_Az_hi);
    cudaGetSymbolAddress((void**)&az_l, g_Az_lo);
    cudaGetSymbolAddress((void**)&ah_h, g_Ah_hi);
    cudaGetSymbolAddress((void**)&ah_l, g_Ah_lo);

    static int attrs_set = 0;
    if (!attrs_set) {
        cudaFuncSetAttribute(scan_kernel, cudaFuncAttributeMaxDynamicSharedMemorySize, SMEM_BYTES);
        attrs_set = 1;
    }

    prep_kernel<<<1680, 256>>>(W_ih, W_hh);
    prep2_kernel<<<4, 256>>>(prior_b1, dobs_b1, drew_b1, dcont_b1);
    prep3_kernel<<<3392, 256>>>(post_W1, prior_W1, dobs_W1, drew_W1, dcont_W1,
                                dobs_W2, prior_W2);
    cvt_obs_kernel<<<BT * 1024 / 4 / 256, 256>>>(obs);

    // Phase A: o_proj = obs @ W1o + post_b1  (tensor, split-bf16, pre-split A)
    mmagemm_kernel<<<dim3(4, BT / 128), 256>>>(
        1024, ao_h, ao_l, 1024, wo_h, wo_l, 256, post_b1, oproj_p, 256, 0,
        nullptr, nullptr, 0);

    // Phase B: persistent sequential scan (tensor-core GRU)
    scan_kernel<<<NCTA, 256, SMEM_BYTES>>>(out, act, eps, b_ih, b_hh,
                                           post_W1, post_W2, post_b2);

    // convert [h|z] rows of out -> g_Az
    cvt_out_kernel<<<BT * 80 / 256, 256>>>(out);

    // Phase C: merged decoder/prior L1 — cols<512 dual-written as bf16 (g_Ah)
    mmagemm_kernel<<<dim3(16, BT / 128), 256>>>(
        320, az_h, az_l, 320, wc_h, wc_l, 1024, bcat_p, hid3_p, 1024, 1,
        ah_h, ah_l, 512);
    // prior L2 (mean/std)
    mmagemm_kernel<<<dim3(1, BT / 128), 256>>>(
        256, ah_h, ah_l, 512, wp_h, wp_l, 64, prior_b2, out + 288, OUT_D, 2,
        nullptr, nullptr, 0);
    // obs decoder L2
    mmagemm_kernel<<<dim3(16, BT / 128), 256>>>(
        256, ah_h + 256, ah_l + 256, 512, wd_h, wd_l, 1024, dobs_b2, out + 416, OUT_D, 0,
        nullptr, nullptr, 0);
    // reward / continuation heads
    gemv_kernel<<<BT / 8, 256>>>(hid3_p + 512, 1024, drew_W2, drew_b2, out + 1440, 0);
    gemv_kernel<<<BT / 8, 256>>>(hid3_p + 768, 1024, dcont_W2, dcont_b2, out + 1441, 3);
}

// round 16
// speedup vs baseline: 1.5632x; 1.0214x over previous
#include <cuda_runtime.h>
#include <cuda_bf16.h>
#include <cstdint>
#include <math.h>

#define T_STEPS 512
#define B_SZ    128
#define BT      (B_SZ * T_STEPS)
#define OUT_D   1442
#define NCTA    128

typedef unsigned long long ull;

// ---------------- scratch (static device globals; no allocation) ----------------
__device__ __align__(16) float g_oproj[BT * 256];
__device__ __align__(16) float g_hid3 [(size_t)BT * 1024];
__device__ __align__(16) float g_bcat [1024];
__device__ __align__(16) float g_part [B_SZ * 16 * 64];
__device__ __align__(16) float g_state[B_SZ * 256];
__device__ unsigned g_cnts[8 * 32];

// GRU weights bf16-split, [k][n] layout (n = gate*256 + hcol)
__device__ __align__(16) __nv_bfloat16 g_Wih_hi[304 * 768], g_Wih_lo[304 * 768];
__device__ __align__(16) __nv_bfloat16 g_Whh_hi[256 * 768], g_Whh_lo[256 * 768];

// bf16-split weights in [k][n] layout (hi + lo)
__device__ __align__(16) __nv_bfloat16 g_Wo_hi[1024 * 256], g_Wo_lo[1024 * 256];
__device__ __align__(16) __nv_bfloat16 g_Wc_hi[320 * 1024], g_Wc_lo[320 * 1024];
__device__ __align__(16) __nv_bfloat16 g_Wd_hi[256 * 1024], g_Wd_lo[256 * 1024];
__device__ __align__(16) __nv_bfloat16 g_Wp_hi[256 * 64],   g_Wp_lo[256 * 64];

// pre-split A matrices (bf16 hi/lo), row-major [row][k]
__device__ __align__(16) __nv_bfloat16 g_Ao_hi[(size_t)BT * 1024], g_Ao_lo[(size_t)BT * 1024];
__device__ __align__(16) __nv_bfloat16 g_Az_hi[(size_t)BT * 320],  g_Az_lo[(size_t)BT * 320];
__device__ __align__(16) __nv_bfloat16 g_Ah_hi[(size_t)BT * 512],  g_Ah_lo[(size_t)BT * 512];

__device__ __forceinline__ float sigmoidf_(float x) { return 1.f / (1.f + expf(-x)); }
__device__ __forceinline__ float softplusf_(float x) {
    return fmaxf(x, 0.f) + log1pf(expf(-fabsf(x)));
}

// bf16 split packers
__device__ __forceinline__ uint32_t pack_hi2(float a, float b) {
    __nv_bfloat16 ha = __float2bfloat16(a), hb = __float2bfloat16(b);
    return (uint32_t)__bfloat16_as_ushort(ha) | ((uint32_t)__bfloat16_as_ushort(hb) << 16);
}
__device__ __forceinline__ uint32_t pack_lo2(float a, float b) {
    __nv_bfloat16 ha = __float2bfloat16(a), hb = __float2bfloat16(b);
    float la = a - __bfloat162float(ha), lb = b - __bfloat162float(hb);
    return (uint32_t)__bfloat16_as_ushort(__float2bfloat16(la))
         | ((uint32_t)__bfloat16_as_ushort(__float2bfloat16(lb)) << 16);
}

// packed fp32x2 helpers
__device__ __forceinline__ void fma2(ull& d, ull a, ull b) {
    asm("fma.rn.f32x2 %0, %1, %2, %0;" : "+l"(d) : "l"(a), "l"(b));
}
__device__ __forceinline__ void add2(ull& d, ull a) {
    asm("add.rn.f32x2 %0, %0, %1;" : "+l"(d) : "l"(a));
}
__device__ __forceinline__ float2 unpack2(ull v) {
    float2 f; asm("mov.b64 {%0, %1}, %2;" : "=f"(f.x), "=f"(f.y) : "l"(v)); return f;
}

// L2-direct loads
__device__ __forceinline__ float4 ldcg4(const float* p) {
    float4 v;
    asm volatile("ld.global.cg.v4.f32 {%0,%1,%2,%3}, [%4];"
                 : "=f"(v.x), "=f"(v.y), "=f"(v.z), "=f"(v.w) : "l"(p));
    return v;
}
__device__ __forceinline__ float ldcg1(const float* p) {
    float v;
    asm volatile("ld.global.cg.f32 %0, [%1];" : "=f"(v) : "l"(p));
    return v;
}

// scoped-atomic barrier primitives
__device__ __forceinline__ void bar_arrive(unsigned* cnt) {
    if (threadIdx.x == 0)
        asm volatile("red.release.gpu.global.add.u32 [%0], %1;" :: "l"(cnt), "r"(1u) : "memory");
}
__device__ __forceinline__ void bar_wait(unsigned* cnt, unsigned target) {
    if (threadIdx.x == 0) {
        unsigned v;
        do {
            asm volatile("ld.acquire.gpu.global.u32 %0, [%1];" : "=r"(v) : "l"(cnt) : "memory");
        } while (v < target);
    }
    __syncthreads();
}

// ---------------- mma.sync helpers ----------------
__device__ __forceinline__ uint32_t smem_u32(const void* p) {
    uint32_t a;
    asm("{ .reg .u64 t; cvta.to.shared.u64 t, %1; cvt.u32.u64 %0, t; }" : "=r"(a) : "l"(p));
    return a;
}
__device__ __forceinline__ void ldsm4(uint32_t* r, uint32_t addr) {
    asm volatile("ldmatrix.sync.aligned.m8n8.x4.shared.b16 {%0,%1,%2,%3}, [%4];"
                 : "=r"(r[0]), "=r"(r[1]), "=r"(r[2]), "=r"(r[3]) : "r"(addr));
}
__device__ __forceinline__ void ldsm4t(uint32_t* r, uint32_t addr) {
    asm volatile("ldmatrix.sync.aligned.m8n8.x4.trans.shared.b16 {%0,%1,%2,%3}, [%4];"
                 : "=r"(r[0]), "=r"(r[1]), "=r"(r[2]), "=r"(r[3]) : "r"(addr));
}
__device__ __forceinline__ void mma16816(float* c, const uint32_t* a, uint32_t b0, uint32_t b1) {
    asm volatile("mma.sync.aligned.m16n8k16.row.col.f32.bf16.bf16.f32 "
                 "{%0,%1,%2,%3}, {%4,%5,%6,%7}, {%8,%9}, {%0,%1,%2,%3};"
                 : "+f"(c[0]), "+f"(c[1]), "+f"(c[2]), "+f"(c[3])
                 : "r"(a[0]), "r"(a[1]), "r"(a[2]), "r"(a[3]), "r"(b0), "r"(b1));
}
__device__ __forceinline__ void cpa16(uint32_t dst, const void* src) {
    asm volatile("cp.async.ca.shared.global [%0], [%1], 16;" :: "r"(dst), "l"(src));
}
#define CP_COMMIT() asm volatile("cp.async.commit_group;")
#define CP_WAIT1()  asm volatile("cp.async.wait_group 1;")
#define CP_WAIT0()  asm volatile("cp.async.wait_group 0;")

// ---------------- prep: split GRU weights bf16 hi/lo ----------------
__global__ void prep_kernel(const float* __restrict__ W_ih, const float* __restrict__ W_hh) {
    if (blockIdx.x == 0 && threadIdx.x < 8) g_cnts[threadIdx.x * 32] = 0u;
    int idx = blockIdx.x * 256 + threadIdx.x;
    const int n1 = 304 * 768;
    float w; __nv_bfloat16 *hi, *lo; int off;
    if (idx < n1) { w = W_ih[idx]; hi = g_Wih_hi; lo = g_Wih_lo; off = idx; }
    else { off = idx - n1; w = W_hh[off]; hi = g_Whh_hi; lo = g_Whh_lo; }
    __nv_bfloat16 h = __float2bfloat16(w);
    hi[off] = h;
    lo[off] = __float2bfloat16(w - __bfloat162float(h));
}

// bias concat for Wcat
__global__ void prep2_kernel(const float* __restrict__ prior_b1, const float* __restrict__ dobs_b1,
                             const float* __restrict__ drew_b1,  const float* __restrict__ dcont_b1)
{
    int j = blockIdx.x * 256 + threadIdx.x;
    int g = j >> 8, jj = j & 255;
    float b;
    if (g == 0)      b = prior_b1[jj];
    else if (g == 1) b = dobs_b1[jj];
    else if (g == 2) b = drew_b1[jj];
    else             b = dcont_b1[jj];
    g_bcat[j] = b;
}

// build bf16-split weights, [k][n] layout
__global__ void prep3_kernel(const float* __restrict__ post_W1,
                             const float* __restrict__ prior_W1, const float* __restrict__ dobs_W1,
                             const float* __restrict__ drew_W1,  const float* __restrict__ dcont_W1,
                             const float* __restrict__ dobs_W2,  const float* __restrict__ prior_W2)
{
    const int No = 1024 * 256, Nc = 320 * 1024, Nd = 256 * 1024;
    int idx = blockIdx.x * 256 + threadIdx.x;
    float w; __nv_bfloat16* hi; __nv_bfloat16* lo; int off;
    if (idx < No) {
        int k = idx >> 8, n = idx & 255;
        w = post_W1[(size_t)(256 + k) * 256 + n];
        hi = g_Wo_hi; lo = g_Wo_lo; off = idx;
    } else if (idx < No + Nc) {
        int r = idx - No;
        int k = r >> 10, n = r & 1023;
        int g = n >> 8, j = n & 255;
        if (k >= 288) w = 0.f;
        else if (g == 0) w = (k < 256) ? prior_W1[k * 256 + j] : 0.f;
        else if (g == 1) w = dobs_W1[(size_t)k * 256 + j];
        else if (g == 2) w = drew_W1[(size_t)k * 256 + j];
        else             w = dcont_W1[(size_t)k * 256 + j];
        hi = g_Wc_hi; lo = g_Wc_lo; off = r;
    } else if (idx < No + Nc + Nd) {
        int r = idx - No - Nc;
        w = dobs_W2[r];
        hi = g_Wd_hi; lo = g_Wd_lo; off = r;
    } else {
        int r = idx - No - Nc - Nd;
        w = prior_W2[r];
        hi = g_Wp_hi; lo = g_Wp_lo; off = r;
    }
    __nv_bfloat16 h = __float2bfloat16(w);
    hi[off] = h;
    lo[off] = __float2bfloat16(w - __bfloat162float(h));
}

// convert obs -> g_Ao (hi/lo)
__global__ void cvt_obs_kernel(const float* __restrict__ obs) {
    size_t i = ((size_t)blockIdx.x * 256 + threadIdx.x) * 4;
    float4 v = *(const float4*)(obs + i);
    *(uint2*)(g_Ao_hi + i) = make_uint2(pack_hi2(v.x, v.y), pack_hi2(v.z, v.w));
    *(uint2*)(g_Ao_lo + i) = make_uint2(pack_lo2(v.x, v.y), pack_lo2(v.z, v.w));
}

// zero-pad g_Az cols 288..319 (once)
__global__ void pad_kernel() {
    size_t i = (size_t)blockIdx.x * 256 + threadIdx.x;   // BT*32
    size_t row = i >> 5;
    int cc = (int)(i & 31) + 288;
    __nv_bfloat16 z = __float2bfloat16(0.f);
    g_Az_hi[row * 320 + cc] = z;
    g_Az_lo[row * 320 + cc] = z;
}

// ---------------- split-bf16 tensor GEMM, cp.async double-buffered ----------------
#define AP 40
#define BP 72
// dynamic smem layout (bytes): A hi buf0/1 @0/10240, A lo @20480/30720,
// B hi @40960/45568, B lo @50176/54784
#define TCB_SMEM 59392

__global__ void __launch_bounds__(256) mmagemm_kernel(
    int K, const __nv_bfloat16* __restrict__ Ahi_g, const __nv_bfloat16* __restrict__ Alo_g, int ldA,
    const __nv_bfloat16* __restrict__ Whi, const __nv_bfloat16* __restrict__ Wlo, int ldw,
    const float* __restrict__ bias, float* __restrict__ C, int ldc, int act,
    __nv_bfloat16* __restrict__ Chi, __nv_bfloat16* __restrict__ Clo, int bfN)
{
    extern __shared__ char smg[];
    const uint32_t smgB = smem_u32(smg);

    const int tid = threadIdx.x, lane = tid & 31, wid = tid >> 5;
    const int warp_m = wid & 3, warp_n = wid >> 2;
    const int rowBase = blockIdx.y * 128, colBase = blockIdx.x * 64;

    float acc[2][4][4];
#pragma unroll
    for (int mt = 0; mt < 2; mt++)
#pragma unroll
        for (int nt = 0; nt < 4; nt++)
#pragma unroll
            for (int i = 0; i < 4; i++) acc[mt][nt][i] = 0.f;

    // per-thread staging addresses
    const int ar = tid >> 1, akh = (tid & 1) * 16;
    const int bk = tid >> 3, bn = (tid & 7) * 8;

    auto stage = [&](int kk, int buf) {
        uint32_t aoff = (uint32_t)buf * 10240 + (ar * AP + akh) * 2;
        size_t asrc = (size_t)(rowBase + ar) * ldA + kk + akh;
        cpa16(smgB + aoff,          Ahi_g + asrc);
        cpa16(smgB + aoff + 16,     Ahi_g + asrc + 8);
        cpa16(smgB + 20480 + aoff,          Alo_g + asrc);
        cpa16(smgB + 20480 + aoff + 16,     Alo_g + asrc + 8);
        uint32_t boff = (uint32_t)buf * 4608 + (bk * BP + bn) * 2;
        size_t bsrc = (size_t)(kk + bk) * ldw + colBase + bn;
        cpa16(smgB + 40960 + boff, Whi + bsrc);
        cpa16(smgB + 50176 + boff, Wlo + bsrc);
    };

    const int nch = K >> 5;
    stage(0, 0);
    CP_COMMIT();

    for (int ch = 0; ch < nch; ch++) {
        if (ch + 1 < nch) {
            stage((ch + 1) << 5, (ch + 1) & 1);
            CP_COMMIT();
            CP_WAIT1();
        } else {
            CP_WAIT0();
        }
        __syncthreads();

        const int buf = ch & 1;
        const uint32_t aHiB = smgB + buf * 10240;
        const uint32_t aLoB = smgB + 20480 + buf * 10240;
        const uint32_t bHiB = smgB + 40960 + buf * 4608;
        const uint32_t bLoB = smgB + 50176 + buf * 4608;

#pragma unroll
        for (int k16 = 0; k16 < 32; k16 += 16) {
            uint32_t ah[2][4], al[2][4], bh[2][4], bl[2][4];
#pragma unroll
            for (int mt = 0; mt < 2; mt++) {
                uint32_t off = ((warp_m * 32 + mt * 16 + (lane & 15)) * AP
                                + k16 + ((lane >> 4) << 3)) * 2;
                ldsm4(ah[mt], aHiB + off);
                ldsm4(al[mt], aLoB + off);
            }
#pragma unroll
            for (int np = 0; np < 2; np++) {
                uint32_t off = ((k16 + (lane & 15)) * BP
                                + warp_n * 32 + np * 16 + ((lane >> 4) << 3)) * 2;
                ldsm4t(bh[np], bHiB + off);
                ldsm4t(bl[np], bLoB + off);
            }
#pragma unroll
            for (int mt = 0; mt < 2; mt++)
#pragma unroll
                for (int nt = 0; nt < 4; nt++) {
                    int np = nt >> 1, bi = (nt & 1) * 2;
                    mma16816(acc[mt][nt], ah[mt], bh[np][bi], bh[np][bi + 1]);
                    mma16816(acc[mt][nt], ah[mt], bl[np][bi], bl[np][bi + 1]);
                    mma16816(acc[mt][nt], al[mt], bh[np][bi], bh[np][bi + 1]);
                }
        }
        __syncthreads();
    }

    const bool bfpath = (Chi != nullptr) && (colBase < bfN);
#pragma unroll
    for (int mt = 0; mt < 2; mt++) {
#pragma unroll
        for (int nt = 0; nt < 4; nt++) {
            int row0 = rowBase + warp_m * 32 + mt * 16 + (lane >> 2);
            int col  = colBase + warp_n * 32 + (nt >> 1) * 16 + (nt & 1) * 8 + (lane & 3) * 2;
            float v0 = acc[mt][nt][0], v1 = acc[mt][nt][1];
            float v2 = acc[mt][nt][2], v3 = acc[mt][nt][3];
            if (bias) {
                float b0 = bias[col], b1 = bias[col + 1];
                v0 += b0; v1 += b1; v2 += b0; v3 += b1;
            }
            if (act == 1) {
                v0 = fmaxf(v0, 0.f); v1 = fmaxf(v1, 0.f);
                v2 = fmaxf(v2, 0.f); v3 = fmaxf(v3, 0.f);
            } else if (act == 2) {
                if (col >= 32)     { v0 = softplusf_(v0) + 0.1f; v2 = softplusf_(v2) + 0.1f; }
                if (col + 1 >= 32) { v1 = softplusf_(v1) + 0.1f; v3 = softplusf_(v3) + 0.1f; }
            }
            if (bfpath) {
                size_t o0 = (size_t)row0 * bfN + col;
                size_t o1 = (size_t)(row0 + 8) * bfN + col;
                *(uint32_t*)(Chi + o0) = pack_hi2(v0, v1);
                *(uint32_t*)(Clo + o0) = pack_lo2(v0, v1);
                *(uint32_t*)(Chi + o1) = pack_hi2(v2, v3);
                *(uint32_t*)(Clo + o1) = pack_lo2(v2, v3);
            } else {
                *(float2*)(C + (size_t)row0 * ldc + col)       = make_float2(v0, v1);
                *(float2*)(C + (size_t)(row0 + 8) * ldc + col) = make_float2(v2, v3);
            }
        }
    }
}

// ---------------- persistent scan kernel: tensor-core GRU ----------------
#define SB_WIH_HI 0
#define SB_WIH_LO 29184
#define SB_WHH_HI 58368
#define SB_WHH_LO 82944
#define SB_W1H    107520
#define SB_W2     124160
#define SB_B2     189696
#define SB_XS     189952
#define SB_XBH    189952
#define SB_XBL    199680
#define SB_HST    209664
#define SB_O64    210752
#define SB_STG    214848
#define SB_EBUF   220992
#define SB_ABUF   223040
#define SB_GBUF   224064
#define SMEM_BYTES 230720

__global__ void __launch_bounds__(256, 1) scan_kernel(
    float* __restrict__ out, const float* __restrict__ act_seq,
    const float* __restrict__ eps,
    const float* __restrict__ b_ih, const float* __restrict__ b_hh,
    const float* __restrict__ post_W1, const float* __restrict__ post_W2,
    const float* __restrict__ post_b2)
{
    extern __shared__ char smb[];
    __nv_bfloat16* wih_h = (__nv_bfloat16*)(smb + SB_WIH_HI);
    __nv_bfloat16* wih_l = (__nv_bfloat16*)(smb + SB_WIH_LO);
    __nv_bfloat16* whh_h = (__nv_bfloat16*)(smb + SB_WHH_HI);
    __nv_bfloat16* whh_l = (__nv_bfloat16*)(smb + SB_WHH_LO);
    float* w1hs = (float*)(smb + SB_W1H);
    float* w2s  = (float*)(smb + SB_W2);
    float* b2s  = (float*)(smb + SB_B2);
    float* xs   = (float*)(smb + SB_XS);
    __nv_bfloat16* xbh = (__nv_bfloat16*)(smb + SB_XBH);
    __nv_bfloat16* xbl = (__nv_bfloat16*)(smb + SB_XBL);
    float* hst  = (float*)(smb + SB_HST);
    float* o64s = (float*)(smb + SB_O64);
    float* stg  = (float*)(smb + SB_STG);
    float* ebuf = (float*)(smb + SB_EBUF);
    float* abuf = (float*)(smb + SB_ABUF);
    float* gbuf = (float*)(smb + SB_GBUF);

    const int tid = threadIdx.x;
    const int lane = tid & 31, wid = tid >> 5;
    const int c   = blockIdx.x;
    const int jt  = c & 15;
    const int bt  = c >> 4;
    const int jl  = tid >> 4;
    const int bl  = tid & 15;
    const int jc  = jt * 16 + jl;
    const int b_a = bt * 16 + bl;
    unsigned* cnt = &g_cnts[bt * 32];

    for (int idx = tid; idx < 304 * 48; idx += 256) {
        int k = idx / 48, n = idx - k * 48;
        int col = (n >> 4) * 256 + jt * 16 + (n & 15);
        wih_h[idx] = g_Wih_hi[k * 768 + col];
        wih_l[idx] = g_Wih_lo[k * 768 + col];
    }
    for (int idx = tid; idx < 256 * 48; idx += 256) {
        int k = idx / 48, n = idx - k * 48;
        int col = (n >> 4) * 256 + jt * 16 + (n & 15);
        whh_h[idx] = g_Whh_hi[k * 768 + col];
        whh_l[idx] = g_Whh_lo[k * 768 + col];
    }
    for (int idx = tid; idx < 16 * 256; idx += 256) {
        int j_ = idx >> 8, k = idx & 255;
        w1hs[j_ * 260 + k] = post_W1[(size_t)k * 256 + jt * 16 + j_];
    }
    for (int idx = tid; idx < 16384; idx += 256) w2s[idx] = post_W2[idx];
    if (tid < 64) b2s[tid] = post_b2[tid];
    __syncthreads();

    const int gcol = jt * 16 + (tid & 15);
    const float bir = b_ih[gcol], biz = b_ih[gcol + 256], bin_ = b_ih[gcol + 512];
    const float bhr = b_hh[gcol], bhz = b_hh[gcol + 256], bhn = b_hh[gcol + 512];

    const uint32_t xbhB = smem_u32(xbh), xblB = smem_u32(xbl);
    const uint32_t wihhB = smem_u32(wih_h), wihlB = smem_u32(wih_l);
    const uint32_t whhhB = smem_u32(whh_h), whhlB = smem_u32(whh_l);

    unsigned barv = 0;

    for (int t = 0; t < T_STEPS; t++) {
        float oproj_reg = g_oproj[((size_t)b_a * T_STEPS + t) * 256 + jc];

        // ========== Phase A ==========
        if (t == 0) {
            int b_l = tid >> 4, j_l = tid & 15;
            g_state[(bt * 16 + b_l) * 256 + jt * 16 + j_l] = 0.f;
            __syncthreads();
            barv += 16; bar_arrive(cnt);
            size_t row0 = (size_t)(bt * 16 + b_l) * T_STEPS;     // t = 0
            out[row0 * OUT_D + jt * 16 + j_l] = 0.f;
            __nv_bfloat16 z0 = __float2bfloat16(0.f);
            g_Az_hi[row0 * 320 + jt * 16 + j_l] = z0;
            g_Az_lo[row0 * 320 + jt * 16 + j_l] = z0;
            bar_wait(cnt, barv);
        } else {
            float hprev_reg = ldcg1(g_state + (bt * 16 + (tid >> 4)) * 256 + gcol);
            int b_l = tid >> 4, og = (tid & 15) * 4;
            float4 racc = *(const float4*)(b2s + og);
#pragma unroll
            for (int q = 0; q < 16; q++) {
                float4 v = ldcg4(g_part + ((size_t)(bt * 16 + b_l) * 16 + q) * 64 + og);
                racc.x += v.x; racc.y += v.y; racc.z += v.z; racc.w += v.w;
            }
            float4 hv[4];
#pragma unroll
            for (int p = 0; p < 4; p++) {
                int idx = tid + p * 256;
                int bl_ = idx >> 6, k4 = idx & 63;
                hv[p] = ldcg4(g_state + (bt * 16 + bl_) * 256 + k4 * 4);
            }
            *(float4*)(o64s + b_l * 64 + og) = racc;
#pragma unroll
            for (int p = 0; p < 4; p++) {
                int idx = tid + p * 256;
                int bl_ = idx >> 6, k4 = idx & 63;
                *(uint2*)(xbh + bl_ * 304 + k4 * 4) =
                    make_uint2(pack_hi2(hv[p].x, hv[p].y), pack_hi2(hv[p].z, hv[p].w));
                *(uint2*)(xbl + bl_ * 304 + k4 * 4) =
                    make_uint2(pack_lo2(hv[p].x, hv[p].y), pack_lo2(hv[p].z, hv[p].w));
            }
            {
                int bl2 = tid >> 4, ka = tid & 15;
                float av = abuf[tid];
                __nv_bfloat16 ah = __float2bfloat16(av);
                xbh[bl2 * 304 + 288 + ka] = ah;
                xbl[bl2 * 304 + 288 + ka] = __float2bfloat16(av - __bfloat162float(ah));
            }
            __syncthreads();
            for (int idx = tid; idx < 512; idx += 256) {
                int bl_ = idx >> 5, s = idx & 31;
                float pm = o64s[bl_ * 64 + s];
                float ps = softplusf_(o64s[bl_ * 64 + 32 + s]) + 0.1f;
                float e  = ebuf[bl_ * 32 + s];
                float z  = fmaf(ps, e, pm);
                __nv_bfloat16 zh = __float2bfloat16(z);
                xbh[bl_ * 304 + 256 + s] = zh;
                xbl[bl_ * 304 + 256 + s] = __float2bfloat16(z - __bfloat162float(zh));
                if (jt == 0) {
                    stg[bl_ * 96 + s]      = pm;
                    stg[bl_ * 96 + 32 + s] = ps;
                    stg[bl_ * 96 + 64 + s] = z;
                }
            }
            __syncthreads();

            if (wid < 6) {
                const int part = wid / 3;
                const int n16  = wid % 3;
                const uint32_t bHiB = part ? whhhB : wihhB;
                const uint32_t bLoB = part ? whhlB : wihlB;
                const int nk16 = part ? 16 : 19;
                float c0[4] = {0, 0, 0, 0}, c1[4] = {0, 0, 0, 0};
#pragma unroll 1
                for (int k16i = 0; k16i < nk16; k16i++) {
                    int k16 = k16i * 16;
                    uint32_t ah[4], al[4], bh[4], blo[4];
                    uint32_t aoff = ((lane & 15) * 304 + k16 + ((lane >> 4) << 3)) * 2;
                    ldsm4(ah, xbhB + aoff);
                    ldsm4(al, xblB + aoff);
                    uint32_t boff = ((k16 + (lane & 15)) * 48 + n16 * 16 + ((lane >> 4) << 3)) * 2;
                    ldsm4t(bh, bHiB + boff);
                    ldsm4t(blo, bLoB + boff);
                    mma16816(c0, ah, bh[0], bh[1]);
                    mma16816(c0, ah, blo[0], blo[1]);
                    mma16816(c0, al, bh[0], bh[1]);
                    mma16816(c1, ah, bh[2], bh[3]);
                    mma16816(c1, ah, blo[2], blo[3]);
                    mma16816(c1, al, bh[2], bh[3]);
                }
                float* gb = gbuf + part * 832;
                int r0 = lane >> 2, cc = n16 * 16 + (lane & 3) * 2;
                gb[r0 * 52 + cc]           = c0[0];
                gb[r0 * 52 + cc + 1]       = c0[1];
                gb[(r0 + 8) * 52 + cc]     = c0[2];
                gb[(r0 + 8) * 52 + cc + 1] = c0[3];
                gb[r0 * 52 + cc + 8]           = c1[0];
                gb[r0 * 52 + cc + 9]           = c1[1];
                gb[(r0 + 8) * 52 + cc + 8]     = c1[2];
                gb[(r0 + 8) * 52 + cc + 9]     = c1[3];
            }
            __syncthreads();

            {
                int row = tid >> 4, col = tid & 15;
                const float* g0 = gbuf + row * 52;
                const float* g1 = gbuf + 832 + row * 52;
                float sir = g0[col]      + bir;
                float siz = g0[16 + col] + biz;
                float sin_= g0[32 + col] + bin_;
                float shr = g1[col]      + bhr;
                float shz = g1[16 + col] + bhz;
                float shn = g1[32 + col] + bhn;
                float r  = sigmoidf_(sir + shr);
                float zg = sigmoidf_(siz + shz);
                float n  = tanhf(sin_ + r * shn);
                hst[row * 17 + col] = (1.f - zg) * n + zg * hprev_reg;
            }
            __syncthreads();
            {
                int b_l2 = tid >> 4, j_l = tid & 15;
                g_state[(bt * 16 + b_l2) * 256 + jt * 16 + j_l] = hst[b_l2 * 17 + j_l];
            }
            __syncthreads();
            barv += 16; bar_arrive(cnt);
            {
                int b_l2 = tid >> 4, j_l = tid & 15;
                float hv2 = hst[b_l2 * 17 + j_l];
                size_t row = (size_t)(bt * 16 + b_l2) * T_STEPS + t;
                out[row * OUT_D + jt * 16 + j_l] = hv2;
                __nv_bfloat16 hh = __float2bfloat16(hv2);
                g_Az_hi[row * 320 + jt * 16 + j_l] = hh;
                g_Az_lo[row * 320 + jt * 16 + j_l] =
                    __float2bfloat16(hv2 - __bfloat162float(hh));
            }
            if (jt == 0) {
                for (int idx = tid; idx < 512; idx += 256) {
                    int bl_ = idx >> 5, s = idx & 31;
                    size_t row = (size_t)(bt * 16 + bl_) * T_STEPS + (t - 1);
                    float z = stg[bl_ * 96 + 64 + s];
                    out[row * OUT_D + 352 + s] = stg[bl_ * 96 + s];
                    out[row * OUT_D + 384 + s] = stg[bl_ * 96 + 32 + s];
                    out[row * OUT_D + 256 + s] = z;
                    __nv_bfloat16 zh = __float2bfloat16(z);
                    g_Az_hi[row * 320 + 256 + s] = zh;
                    g_Az_lo[row * 320 + 256 + s] =
                        __float2bfloat16(z - __bfloat162float(zh));
                }
            }
            bar_wait(cnt, barv);
        }

        // ========== Phase BC: hid slice + partial o64 (SIMT f32x2) ==========
        {
            float* hs = xs;
#pragma unroll
            for (int p = 0; p < 4; p++) {
                int idx = tid + p * 256;
                int b_l = idx >> 6, k4 = idx & 63;
                float4 v = ldcg4(g_state + (bt * 16 + b_l) * 256 + k4 * 4);
                *(float4*)(hs + b_l * 260 + k4 * 4) = v;
            }
            __syncthreads();
            const ulonglong2* hv2 = (const ulonglong2*)(hs + bl * 260);
            const ulonglong2* wv2 = (const ulonglong2*)(w1hs + jl * 260);
            ull a0 = 0, a1 = 0;
#pragma unroll 8
            for (int k4 = 0; k4 < 64; k4++) {
                ulonglong2 h2 = hv2[k4], w2v = wv2[k4];
                fma2(a0, h2.x, w2v.x);
                fma2(a1, h2.y, w2v.y);
            }
            add2(a0, a1);
            float2 f = unpack2(a0);
            float acc = f.x + f.y + oproj_reg;
            hst[bl * 17 + jl] = fmaxf(acc, 0.f);
            __syncthreads();
            const int o = tid & 63, bq = tid >> 6;
#pragma unroll
            for (int bb = 0; bb < 4; bb++) {
                int b_l = bq * 4 + bb;
                float pacc = 0.f;
#pragma unroll
                for (int k = 0; k < 16; k++)
                    pacc = fmaf(hst[b_l * 17 + k], w2s[(jt * 16 + k) * 64 + o], pacc);
                g_part[((size_t)(bt * 16 + b_l) * 16 + jt) * 64 + o] = pacc;
            }
            __syncthreads();
            barv += 16; bar_arrive(cnt);
            {
                float2 ev = *(const float2*)(eps + ((size_t)t * B_SZ + bt * 16) * 32 + tid * 2);
                *(float2*)(ebuf + tid * 2) = ev;
                abuf[tid] = act_seq[((size_t)(bt * 16 + (tid >> 4)) * T_STEPS + t) * 16 + (tid & 15)];
            }
            bar_wait(cnt, barv);
        }
    }

    // ========== epilogue: reduce partials for t=511, write outputs ==========
    {
        const int b = c;
        if (tid < 64) {
            float acc = b2s[tid];
#pragma unroll
            for (int q = 0; q < 16; q++)
                acc += ldcg1(g_part + ((size_t)b * 16 + q) * 64 + tid);
            o64s[tid] = acc;
        }
        __syncthreads();
        if (tid < 32) {
            int s = tid;
            float pm = o64s[s];
            float ps = softplusf_(o64s[32 + s]) + 0.1f;
            float e  = eps[((size_t)(T_STEPS - 1) * B_SZ + b) * 32 + s];
            float z  = fmaf(ps, e, pm);
            size_t row = (size_t)b * T_STEPS + (T_STEPS - 1);
            out[row * OUT_D + 352 + s] = pm;
            out[row * OUT_D + 384 + s] = ps;
            out[row * OUT_D + 256 + s] = z;
            __nv_bfloat16 zh = __float2bfloat16(z);
            g_Az_hi[row * 320 + 256 + s] = zh;
            g_Az_lo[row * 320 + 256 + s] = __float2bfloat16(z - __bfloat162float(zh));
        }
    }
}

// ---------------- GEMV (N=1): K=256 ----------------
__global__ void gemv_kernel(const float* __restrict__ A, int lda,
                            const float* __restrict__ w,
                            const float* __restrict__ bias, float* __restrict__ C, int act)
{
    const int warp = threadIdx.x >> 5, lane = threadIdx.x & 31;
    const int row = blockIdx.x * 8 + warp;
    const float* a = A + (size_t)row * lda;
    float acc = 0.f;
#pragma unroll
    for (int i = 0; i < 8; i++) acc = fmaf(a[lane + 32 * i], w[lane + 32 * i], acc);
#pragma unroll
    for (int off = 16; off; off >>= 1) acc += __shfl_xor_sync(0xffffffffu, acc, off);
    if (lane == 0) {
        float v = acc + bias[0];
        if (act == 3) v = sigmoidf_(v);
        C[(size_t)row * OUT_D] = v;
    }
}

// ---------------- driver ----------------
extern "C" void kernel_launch(void* const* d_in, const int* in_sizes, int n_in,
                              void* d_out, int out_size)
{
    const float* obs      = (const float*)d_in[0];
    const float* act      = (const float*)d_in[1];
    const float* eps      = (const float*)d_in[2];
    const float* prior_W1 = (const float*)d_in[3];
    const float* prior_b1 = (const float*)d_in[4];
    const float* prior_W2 = (const float*)d_in[5];
    const float* prior_b2 = (const float*)d_in[6];
    const float* post_W1  = (const float*)d_in[7];
    const float* post_b1  = (const float*)d_in[8];
    const float* post_W2  = (const float*)d_in[9];
    const float* post_b2  = (const float*)d_in[10];
    const float* W_ih     = (const float*)d_in[11];
    const float* b_ih     = (const float*)d_in[12];
    const float* W_hh     = (const float*)d_in[13];
    const float* b_hh     = (const float*)d_in[14];
    const float* dobs_W1  = (const float*)d_in[15];
    const float* dobs_b1  = (const float*)d_in[16];
    const float* dobs_W2  = (const float*)d_in[17];
    const float* dobs_b2  = (const float*)d_in[18];
    const float* drew_W1  = (const float*)d_in[19];
    const float* drew_b1  = (const float*)d_in[20];
    const float* drew_W2  = (const float*)d_in[21];
    const float* drew_b2  = (const float*)d_in[22];
    const float* dcont_W1 = (const float*)d_in[23];
    const float* dcont_b1 = (const float*)d_in[24];
    const float* dcont_W2 = (const float*)d_in[25];
    const float* dcont_b2 = (const float*)d_in[26];
    float* out = (float*)d_out;

    float *oproj_p = nullptr, *hid3_p = nullptr, *bcat_p = nullptr;
    cudaGetSymbolAddress((void**)&oproj_p, g_oproj);
    cudaGetSymbolAddress((void**)&hid3_p, g_hid3);
    cudaGetSymbolAddress((void**)&bcat_p, g_bcat);
    __nv_bfloat16 *wo_h, *wo_l, *wc_h, *wc_l, *wd_h, *wd_l, *wp_h, *wp_l;
    __nv_bfloat16 *ao_h, *ao_l, *az_h, *az_l, *ah_h, *ah_l;
    cudaGetSymbolAddress((void**)&wo_h, g_Wo_hi);
    cudaGetSymbolAddress((void**)&wo_l, g_Wo_lo);
    cudaGetSymbolAddress((void**)&wc_h, g_Wc_hi);
    cudaGetSymbolAddress((void**)&wc_l, g_Wc_lo);
    cudaGetSymbolAddress((void**)&wd_h, g_Wd_hi);
    cudaGetSymbolAddress((void**)&wd_l, g_Wd_lo);
    cudaGetSymbolAddress((void**)&wp_h, g_Wp_hi);
    cudaGetSymbolAddress((void**)&wp_l, g_Wp_lo);
    cudaGetSymbolAddress((void**)&ao_h, g_Ao_hi);
    cudaGetSymbolAddress((void**)&ao_l, g_Ao_lo);
    cudaGetSymbolAddress((void**)&az_h, g_Az_hi);
    cudaGetSymbolAddress((void**)&az_l, g_Az_lo);
    cudaGetSymbolAddress((void**)&ah_h, g_Ah_hi);
    cudaGetSymbolAddress((void**)&ah_l, g_Ah_lo);

    static int attrs_set = 0;
    if (!attrs_set) {
        cudaFuncSetAttribute(scan_kernel, cudaFuncAttributeMaxDynamicSharedMemorySize, SMEM_BYTES);
        cudaFuncSetAttribute(mmagemm_kernel, cudaFuncAttributeMaxDynamicSharedMemorySize, TCB_SMEM);
        attrs_set = 1;
    }

    prep_kernel<<<1680, 256>>>(W_ih, W_hh);
    prep2_kernel<<<4, 256>>>(prior_b1, dobs_b1, drew_b1, dcont_b1);
    prep3_kernel<<<3392, 256>>>(post_W1, prior_W1, dobs_W1, drew_W1, dcont_W1,
                                dobs_W2, prior_W2);
    cvt_obs_kernel<<<BT * 1024 / 4 / 256, 256>>>(obs);
    pad_kernel<<<BT * 32 / 256, 256>>>();

    // Phase A: o_proj = obs @ W1o + post_b1  (tensor, split-bf16, pipelined)
    mmagemm_kernel<<<dim3(4, BT / 128), 256, TCB_SMEM>>>(
        1024, ao_h, ao_l, 1024, wo_h, wo_l, 256, post_b1, oproj_p, 256, 0,
        nullptr, nullptr, 0);

    // Phase B: persistent sequential scan (tensor-core GRU; writes g_Az directly)
    scan_kernel<<<NCTA, 256, SMEM_BYTES>>>(out, act, eps, b_ih, b_hh,
                                           post_W1, post_W2, post_b2);

    // Phase C: merged decoder/prior L1 — cols<512 dual-written as bf16 (g_Ah)
    mmagemm_kernel<<<dim3(16, BT / 128), 256, TCB_SMEM>>>(
        320, az_h, az_l, 320, wc_h, wc_l, 1024, bcat_p, hid3_p, 1024, 1,
        ah_h, ah_l, 512);
    // prior L2 (mean/std)
    mmagemm_kernel<<<dim3(1, BT / 128), 256, TCB_SMEM>>>(
        256, ah_h, ah_l, 512, wp_h, wp_l, 64, prior_b2, out + 288, OUT_D, 2,
        nullptr, nullptr, 0);
    // obs decoder L2
    mmagemm_kernel<<<dim3(16, BT / 128), 256, TCB_SMEM>>>(
        256, ah_h + 256, ah_l + 256, 512, wd_h, wd_l, 1024, dobs_b2, out + 416, OUT_D, 0,
        nullptr, nullptr, 0);
    // reward / continuation heads
    gemv_kernel<<<BT / 8, 256>>>(hid3_p + 512, 1024, drew_W2, drew_b2, out + 1440, 0);
    gemv_kernel<<<BT / 8, 256>>>(hid3_p + 768, 1024, dcont_W2, dcont_b2, out + 1441, 3);
}